// round 11
// baseline (speedup 1.0000x reference)
#include <cuda_runtime.h>
#include <cuda_bf16.h>
#include <math.h>
#include <stdint.h>

#define BB 8
#define NN 2048
#define KK 1024
#define MP 128            // points per block
#define THREADS 512

// ---------------- device state ----------------
__device__ float d_mean0[BB*3], d_mean1[BB*3];
__device__ float d_posesJ[7*12];
__device__ float d_gpose[BB*12];
__device__ float d_igtinv[BB*12];
__device__ float d_estg[BB*12];
__device__ float d_f0[BB*KK], d_fj[BB*6*KK], d_f1[BB*KK];
__device__ float d_J[BB*KK*6];
__device__ float d_Hinv[BB*36];
__device__ float d_r[BB*KK];
__device__ float d_lpart[64];

// ---------------- helpers ----------------
__device__ __forceinline__ void atomicMaxF(float* addr, float val) {
    if (val >= 0.f) atomicMax((int*)addr, __float_as_int(val));
    else            atomicMin((unsigned int*)addr, __float_as_uint(val));
}
__device__ __forceinline__ uint32_t f2tf32(float f) {
    uint32_t r; asm("cvt.rna.tf32.f32 %0, %1;" : "=r"(r) : "f"(f)); return r;
}
__device__ __forceinline__ void split_tf32(float v, float& hi, float& lo) {
    uint32_t h = f2tf32(v);
    hi = __uint_as_float(h);
    lo = __uint_as_float(f2tf32(v - __uint_as_float(h)));
}
__device__ __forceinline__ void mma_tf32(float* d,
    uint32_t a0, uint32_t a1, uint32_t a2, uint32_t a3, uint32_t b0, uint32_t b1) {
    asm volatile(
        "mma.sync.aligned.m16n8k8.row.col.f32.tf32.tf32.f32 "
        "{%0,%1,%2,%3}, {%4,%5,%6,%7}, {%8,%9}, {%0,%1,%2,%3};"
        : "+f"(d[0]), "+f"(d[1]), "+f"(d[2]), "+f"(d[3])
        : "r"(a0), "r"(a1), "r"(a2), "r"(a3), "r"(b0), "r"(b1));
}

// se3_exp (double internals), output 3x4 row-major float
__device__ void se3_exp_d(const double w[3], const double v[3], float out[12]) {
    double t2 = w[0]*w[0] + w[1]*w[1] + w[2]*w[2];
    double t = sqrt(t2);
    double A, Bc, Cc;
    if (t < 1e-6) {
        A  = 1.0 - t2/6.0;  Bc = 0.5 - t2/24.0;  Cc = 1.0/6.0 - t2/120.0;
    } else {
        double st = sin(t), ct = cos(t);
        A = st/t;  Bc = (1.0-ct)/t2;  Cc = (t-st)/(t2*t);
    }
    double W[3][3] = {{0.0,-w[2],w[1]},{w[2],0.0,-w[0]},{-w[1],w[0],0.0}};
    double W2m[3][3];
    for (int i = 0; i < 3; i++)
        for (int j = 0; j < 3; j++)
            W2m[i][j] = w[i]*w[j] - (i==j ? t2 : 0.0);
    double R[3][3], V[3][3];
    for (int i = 0; i < 3; i++)
        for (int j = 0; j < 3; j++) {
            double I = (i==j) ? 1.0 : 0.0;
            R[i][j] = I + A*W[i][j] + Bc*W2m[i][j];
            V[i][j] = I + Bc*W[i][j] + Cc*W2m[i][j];
        }
    for (int i = 0; i < 3; i++) {
        double p = V[i][0]*v[0] + V[i][1]*v[1] + V[i][2]*v[2];
        out[i*4+0] = (float)R[i][0]; out[i*4+1] = (float)R[i][1];
        out[i*4+2] = (float)R[i][2]; out[i*4+3] = (float)p;
    }
}

// ---------------- means ----------------
__global__ void means_kernel(const float* __restrict__ p_tgt, const float* __restrict__ p_src) {
    int b = blockIdx.x, tid = threadIdx.x;
    float a[6] = {0,0,0,0,0,0};
    for (int n = tid; n < NN; n += 256) {
        const float* pt = p_tgt + ((size_t)b*NN + n)*3;
        const float* ps = p_src + ((size_t)b*NN + n)*3;
        a[0] += pt[0]; a[1] += pt[1]; a[2] += pt[2];
        a[3] += ps[0]; a[4] += ps[1]; a[5] += ps[2];
    }
    for (int off = 16; off; off >>= 1)
        #pragma unroll
        for (int q = 0; q < 6; q++) a[q] += __shfl_down_sync(0xffffffffu, a[q], off);
    __shared__ float sm[8][6];
    int lane = tid & 31, w = tid >> 5;
    if (lane == 0) { for (int q = 0; q < 6; q++) sm[w][q] = a[q]; }
    __syncthreads();
    if (tid < 6) {
        float s = 0.f;
        for (int w2 = 0; w2 < 8; w2++) s += sm[w2][tid];
        s *= (1.0f / NN);
        if (tid < 3) d_mean0[b*3 + tid] = s;
        else         d_mean1[b*3 + tid - 3] = s;
    }
}

// ---------------- setup ----------------
__global__ void setup_kernel(const float* __restrict__ dt, const float* __restrict__ igt_twist) {
    int tid = threadIdx.x;
    if (tid < 7) {
        float out[12];
        if (tid == 0) {
            float I[12] = {1,0,0,0, 0,1,0,0, 0,0,1,0};
            for (int i = 0; i < 12; i++) out[i] = I[i];
        } else {
            int j = tid - 1;
            double w[3] = {0,0,0}, v[3] = {0,0,0};
            double val = -(double)__ldg(&dt[j]);
            if (j < 3) w[j] = val; else v[j-3] = val;
            se3_exp_d(w, v, out);
        }
        for (int i = 0; i < 12; i++) d_posesJ[tid*12 + i] = out[i];
    }
    if (tid >= 8 && tid < 16) {
        int b = tid - 8;
        float I[12] = {1,0,0,0, 0,1,0,0, 0,0,1,0};
        for (int i = 0; i < 12; i++) d_gpose[b*12 + i] = I[i];
    }
    if (tid >= 16 && tid < 24) {
        int b = tid - 16;
        double w[3], v[3];
        for (int i = 0; i < 3; i++) { w[i] = igt_twist[b*6 + i]; v[i] = igt_twist[b*6 + 3 + i]; }
        float g[12];
        se3_exp_d(w, v, g);
        float inv[12];
        for (int r = 0; r < 3; r++)
            for (int c = 0; c < 3; c++) inv[r*4 + c] = g[c*4 + r];
        for (int r = 0; r < 3; r++)
            inv[r*4 + 3] = -(g[0*4+r]*g[3] + g[1*4+r]*g[7] + g[2*4+r]*g[11]);
        for (int i = 0; i < 12; i++) d_igtinv[b*12 + i] = inv[i];
    }
}

__global__ void init_f_kernel() {
    int i = blockIdx.x*256 + threadIdx.x;
    if (i < BB*KK) d_f0[i] = -INFINITY;
    else if (i < BB*KK + BB*6*KK) d_fj[i - BB*KK] = -INFINITY;
    else if (i < BB*KK + BB*6*KK + BB*KK) d_f1[i - BB*KK - BB*6*KK] = -INFINITY;
}

// ---------------- fused encode: tf32 MMA with fragment-ordered SMEM ----------------
// 512 threads (16 warps), 128 points.
// AFP: fp32 A fragments [mt(8)][ks(16)][lane(32)] float4 (a0,a1,a2,a3) = 16384 floats.
// BF0/BF1: pre-split tf32 B fragments [ng(2)][ks(16)][nt(4)][lane(32)] float4
//          (bh0,bl0,bh1,bl1) = 16384 floats each (one N-chunk of 64 cols).
// W3 chunk fetched straight to registers (4x LDG.128/thread), split into BF once;
// all inner-loop operand fetches are lane-coalesced LDS.128.
#define OFF_AFP  0
#define OFF_BF0  16384
#define OFF_BF1  32768
#define SMEMF    49152
#define ENC_SMEM_BYTES (SMEMF*4)
// A-phase aliases (inside BF regions, consumed before first BF writes):
#define OFF_PTS  16384          /* 384 */
#define OFF_SW1  16768          /* 192 */
#define OFF_SB1  16960          /* 64  */
#define OFF_SB2  17024          /* 128 */
#define OFF_H1   17152          /* 128 x 68 = 8704 -> ends 25856 < 32768 */
#define OFF_W2   32768          /* 8192 -> ends 40960 < 49152 (in BF1) */

template<int MODE>
__global__ __launch_bounds__(THREADS, 1)
void encode_kernel(const float* __restrict__ P,
                   const float* __restrict__ W1g, const float* __restrict__ b1g,
                   const float* __restrict__ W2g, const float* __restrict__ b2g,
                   const float* __restrict__ W3g, const float* __restrict__ b3g) {
    extern __shared__ float sm[];
    int tid = threadIdx.x;
    int wid = tid >> 5, lane = tid & 31;

    int b; const float* pose; const float* mean; float* out;
    if (MODE == 0) {
        int bm = blockIdx.y;
        b = bm / 7; int m = bm % 7;
        pose = d_posesJ + m*12;
        mean = d_mean0 + b*3;
        out  = (m == 0) ? (d_f0 + b*KK) : (d_fj + ((size_t)b*6 + (m-1))*KK);
    } else {
        b = blockIdx.y;
        pose = d_gpose + b*12;
        mean = d_mean1 + b*3;
        out  = d_f1 + b*KK;
    }

    // ---- phase A0: stage small weights + transform 128 points ----
    {
        const float4* w2v = (const float4*)W2g;
        #pragma unroll
        for (int i = 0; i < 4; i++)
            *(float4*)&sm[OFF_W2 + (tid + i*512)*4] = w2v[tid + i*512];
    }
    if (tid >= 128 && tid < 320) sm[OFF_SW1 + tid - 128] = W1g[tid - 128];
    if (tid >= 320 && tid < 384) sm[OFF_SB1 + tid - 320] = b1g[tid - 320];
    if (tid >= 384 && tid < 512) sm[OFF_SB2 + tid - 384] = b2g[tid - 384];
    if (tid < MP) {
        int n = blockIdx.x * MP + tid;
        const float* pp = P + ((size_t)b*NN + n)*3;
        float dx = pp[0] - mean[0], dy = pp[1] - mean[1], dz = pp[2] - mean[2];
        sm[OFF_PTS + tid*3 + 0] = pose[0]*dx + pose[1]*dy + pose[2]*dz  + pose[3];
        sm[OFF_PTS + tid*3 + 1] = pose[4]*dx + pose[5]*dy + pose[6]*dz  + pose[7];
        sm[OFF_PTS + tid*3 + 2] = pose[8]*dx + pose[9]*dy + pose[10]*dz + pose[11];
    }
    __syncthreads();

    // ---- phase A1: h1 = relu(pt @ W1 + b1), 128 x 64, stride 68 ----
    #pragma unroll
    for (int i = 0; i < 16; i++) {
        int idx = tid + i*512;
        int p = idx >> 6, c1 = idx & 63;
        float x = sm[OFF_PTS + p*3 + 0], y = sm[OFF_PTS + p*3 + 1], z = sm[OFF_PTS + p*3 + 2];
        float v = sm[OFF_SB1 + c1];
        v = fmaf(x, sm[OFF_SW1 + c1],       v);
        v = fmaf(y, sm[OFF_SW1 + 64 + c1],  v);
        v = fmaf(z, sm[OFF_SW1 + 128 + c1], v);
        sm[OFF_H1 + p*68 + c1] = fmaxf(v, 0.f);
    }
    __syncthreads();

    // ---- phase A2: h2 = relu(h1 @ W2 + b2) -> regs -> AFP fragments ----
    float4 acc4[8];
    {
        int p = tid >> 2, rr = tid & 3;
        #pragma unroll
        for (int q = 0; q < 8; q++)
            acc4[q] = *(const float4*)&sm[OFF_SB2 + rr*4 + q*16];
        #pragma unroll
        for (int half = 0; half < 2; half++) {
            float hr[32];
            #pragma unroll
            for (int i = 0; i < 8; i++) {
                float4 h4 = *(const float4*)&sm[OFF_H1 + p*68 + half*32 + i*4];
                hr[i*4+0] = h4.x; hr[i*4+1] = h4.y; hr[i*4+2] = h4.z; hr[i*4+3] = h4.w;
            }
            #pragma unroll
            for (int q = 0; q < 8; q++) {
                int c2 = rr*4 + q*16;
                float4 a = acc4[q];
                #pragma unroll 16
                for (int c1 = 0; c1 < 32; c1++) {
                    float4 w = *(const float4*)&sm[OFF_W2 + (half*32 + c1)*128 + c2];
                    float h = hr[c1];
                    a.x = fmaf(h, w.x, a.x); a.y = fmaf(h, w.y, a.y);
                    a.z = fmaf(h, w.z, a.z); a.w = fmaf(h, w.w, a.w);
                }
                acc4[q] = a;
            }
        }
    }
    // write AFP fragments: value (p=row, c=q*16+rr*4+j):
    //   ks = q*2 + (rr>>1), tg = j, hi4 = rr&1; mt = p>>4, r = p&15, g = r&7, upper = r>>3
    {
        int p = tid >> 2, rr = tid & 3;
        int mt = p >> 4, r = p & 15, g = r & 7, upper = r >> 3;
        int hi4 = rr & 1, kbase = rr >> 1;
        #pragma unroll
        for (int q = 0; q < 8; q++) {
            int ks = q*2 + kbase;
            float vv[4] = { fmaxf(acc4[q].x,0.f), fmaxf(acc4[q].y,0.f),
                            fmaxf(acc4[q].z,0.f), fmaxf(acc4[q].w,0.f) };
            #pragma unroll
            for (int j = 0; j < 4; j++)
                sm[OFF_AFP + (((mt*16 + ks)*32) + g*4 + j)*4 + (upper + 2*hi4)] = vv[j];
        }
    }
    __syncthreads();   // AFP ready; H1/W2 alias regions (BF0/BF1) free

    // ---- phase B: 16 N-chunks of 64 cols ----
    int mt = wid & 7, ng2 = wid >> 3;
    int g = lane >> 2, tg = lane & 3;
    const float* Af = &sm[OFF_AFP + (mt*16*32 + lane)*4];

    // split-pass roles: thread = (pr = tid>>3, nblk = tid&7)
    int spr = tid >> 3, snb = tid & 7;
    int sks = spr >> 2, stg = spr & 3;
    int sng = snb >> 2, snt = snb & 3;
    int sc0 = sks*8 + stg;
    const float* w3r0 = W3g + (size_t)sc0*1024 + snb*8;
    const float* w3r1 = w3r0 + 4*1024;
    int sfrag = (((sng*16 + sks)*4 + snt)*32)*4;   // float index base (element j*4+stg added later)

    float4 v00 = *(const float4*)(w3r0);
    float4 v01 = *(const float4*)(w3r0 + 4);
    float4 v10 = *(const float4*)(w3r1);
    float4 v11 = *(const float4*)(w3r1 + 4);

    for (int ch = 0; ch < 16; ch++) {
        float* BF = &sm[(ch & 1) ? OFF_BF1 : OFF_BF0];
        // split 8 (c,c+4,n) items into fragment-order BF
        {
            float s0[8] = {v00.x, v00.y, v00.z, v00.w, v01.x, v01.y, v01.z, v01.w};
            float s1[8] = {v10.x, v10.y, v10.z, v10.w, v11.x, v11.y, v11.z, v11.w};
            #pragma unroll
            for (int j = 0; j < 8; j++) {
                float h0, l0, h1, l1;
                split_tf32(s0[j], h0, l0);
                split_tf32(s1[j], h1, l1);
                *(float4*)&BF[sfrag + (j*4 + stg)*4] = make_float4(h0, l0, h1, l1);
            }
        }
        if (ch < 15) {
            const float* n0 = w3r0 + (ch + 1)*64;
            const float* n1 = w3r1 + (ch + 1)*64;
            v00 = *(const float4*)(n0);
            v01 = *(const float4*)(n0 + 4);
            v10 = *(const float4*)(n1);
            v11 = *(const float4*)(n1 + 4);
        }
        __syncthreads();   // BF[ch&1] complete (prev readers of it barriered 2 iters ago)

        const float* Bf = &BF[(ng2*16*4*32 + lane)*4];
        float acc[4][4];
        #pragma unroll
        for (int nt = 0; nt < 4; nt++)
            #pragma unroll
            for (int j = 0; j < 4; j++) acc[nt][j] = 0.f;

        #pragma unroll
        for (int ks = 0; ks < 16; ks++) {
            float4 a = *(const float4*)(Af + ks*128);
            float ah0,al0,ah1,al1,ah2,al2,ah3,al3;
            split_tf32(a.x, ah0, al0); split_tf32(a.y, ah1, al1);
            split_tf32(a.z, ah2, al2); split_tf32(a.w, ah3, al3);
            uint32_t uah0 = __float_as_uint(ah0), ual0 = __float_as_uint(al0);
            uint32_t uah1 = __float_as_uint(ah1), ual1 = __float_as_uint(al1);
            uint32_t uah2 = __float_as_uint(ah2), ual2 = __float_as_uint(al2);
            uint32_t uah3 = __float_as_uint(ah3), ual3 = __float_as_uint(al3);
            const float* bp = Bf + ks*512;
            #pragma unroll
            for (int nt = 0; nt < 4; nt++) {
                float4 bf = *(const float4*)(bp + nt*128);
                uint32_t bh0 = __float_as_uint(bf.x), bl0 = __float_as_uint(bf.y);
                uint32_t bh1 = __float_as_uint(bf.z), bl1 = __float_as_uint(bf.w);
                mma_tf32(acc[nt], uah0, uah1, uah2, uah3, bh0, bh1);
                mma_tf32(acc[nt], uah0, uah1, uah2, uah3, bl0, bl1);
                mma_tf32(acc[nt], ual0, ual1, ual2, ual3, bh0, bh1);
            }
        }

        // epilogue: max over 16 rows of this m-tile, then atomicMaxF
        #pragma unroll
        for (int nt = 0; nt < 4; nt++) {
            float m0 = fmaxf(acc[nt][0], acc[nt][2]);
            float m1 = fmaxf(acc[nt][1], acc[nt][3]);
            #pragma unroll
            for (int off = 4; off < 32; off <<= 1) {
                m0 = fmaxf(m0, __shfl_xor_sync(0xffffffffu, m0, off));
                m1 = fmaxf(m1, __shfl_xor_sync(0xffffffffu, m1, off));
            }
            if (g == 0) {
                int k = ch*64 + ng2*32 + nt*8 + tg*2;
                atomicMaxF(&out[k],     m0 + __ldg(&b3g[k]));
                atomicMaxF(&out[k + 1], m1 + __ldg(&b3g[k + 1]));
            }
        }
    }
}

// ---------------- J and Hinv ----------------
__global__ void jh_kernel(const float* __restrict__ dt) {
    int b = blockIdx.x, tid = threadIdx.x;
    float dtv[6];
    #pragma unroll
    for (int j = 0; j < 6; j++) dtv[j] = __ldg(&dt[j]);
    double hacc[21];
    #pragma unroll
    for (int q = 0; q < 21; q++) hacc[q] = 0.0;
    for (int k = tid; k < KK; k += 256) {
        float f0k = d_f0[b*KK + k];
        float jv[6];
        #pragma unroll
        for (int j = 0; j < 6; j++) {
            jv[j] = (f0k - d_fj[((size_t)b*6 + j)*KK + k]) / dtv[j];
            d_J[((size_t)b*KK + k)*6 + j] = jv[j];
        }
        int q = 0;
        #pragma unroll
        for (int i = 0; i < 6; i++)
            #pragma unroll
            for (int j = i; j < 6; j++)
                hacc[q++] += (double)jv[i] * (double)jv[j];
    }
    for (int off = 16; off; off >>= 1)
        #pragma unroll
        for (int q = 0; q < 21; q++) hacc[q] += __shfl_down_sync(0xffffffffu, hacc[q], off);
    __shared__ double shH[8][21];
    int lane = tid & 31, w = tid >> 5;
    if (lane == 0) { for (int q = 0; q < 21; q++) shH[w][q] = hacc[q]; }
    __syncthreads();
    if (tid == 0) {
        double s[21];
        for (int q = 0; q < 21; q++) { s[q] = 0.0; for (int w2 = 0; w2 < 8; w2++) s[q] += shH[w2][q]; }
        double H[6][6];
        int q = 0;
        for (int i = 0; i < 6; i++)
            for (int j = i; j < 6; j++) { H[i][j] = s[q]; H[j][i] = s[q]; q++; }
        double M[6][12];
        for (int i = 0; i < 6; i++)
            for (int j = 0; j < 12; j++) M[i][j] = (j < 6) ? H[i][j] : ((j - 6 == i) ? 1.0 : 0.0);
        for (int col = 0; col < 6; col++) {
            int piv = col; double best = fabs(M[col][col]);
            for (int r2 = col + 1; r2 < 6; r2++)
                if (fabs(M[r2][col]) > best) { best = fabs(M[r2][col]); piv = r2; }
            if (piv != col)
                for (int j = 0; j < 12; j++) { double t = M[col][j]; M[col][j] = M[piv][j]; M[piv][j] = t; }
            double inv = 1.0 / M[col][col];
            for (int j = 0; j < 12; j++) M[col][j] *= inv;
            for (int r2 = 0; r2 < 6; r2++) {
                if (r2 == col) continue;
                double f = M[r2][col];
                for (int j = 0; j < 12; j++) M[r2][j] -= f * M[col][j];
            }
        }
        for (int i = 0; i < 6; i++)
            for (int j = 0; j < 6; j++) d_Hinv[b*36 + i*6 + j] = (float)M[i][6 + j];
    }
}

// ---------------- Gauss-Newton update (also resets f1) ----------------
__global__ void update_kernel() {
    int b = blockIdx.x, tid = threadIdx.x;
    double u[6] = {0,0,0,0,0,0};
    for (int k = tid; k < KK; k += 256) {
        float r = d_f1[b*KK + k] - d_f0[b*KK + k];
        d_r[b*KK + k] = r;
        d_f1[b*KK + k] = -INFINITY;
        #pragma unroll
        for (int j = 0; j < 6; j++) u[j] += (double)d_J[((size_t)b*KK + k)*6 + j] * (double)r;
    }
    for (int off = 16; off; off >>= 1)
        #pragma unroll
        for (int j = 0; j < 6; j++) u[j] += __shfl_down_sync(0xffffffffu, u[j], off);
    __shared__ double shU[8][6];
    int lane = tid & 31, w = tid >> 5;
    if (lane == 0) { for (int j = 0; j < 6; j++) shU[w][j] = u[j]; }
    __syncthreads();
    if (tid == 0) {
        double uu[6];
        for (int j = 0; j < 6; j++) { uu[j] = 0.0; for (int w2 = 0; w2 < 8; w2++) uu[j] += shU[w2][j]; }
        double dx[6];
        for (int i = 0; i < 6; i++) {
            double s2 = 0.0;
            for (int j = 0; j < 6; j++) s2 += (double)d_Hinv[b*36 + i*6 + j] * uu[j];
            dx[i] = -s2;
        }
        float E[12];
        double wv[3] = {dx[0], dx[1], dx[2]}, vv[3] = {dx[3], dx[4], dx[5]};
        se3_exp_d(wv, vv, E);
        float G[12];
        for (int i = 0; i < 12; i++) G[i] = d_gpose[b*12 + i];
        float Ng[12];
        for (int r2 = 0; r2 < 3; r2++) {
            for (int c = 0; c < 3; c++)
                Ng[r2*4 + c] = E[r2*4+0]*G[0*4+c] + E[r2*4+1]*G[1*4+c] + E[r2*4+2]*G[2*4+c];
            Ng[r2*4 + 3] = E[r2*4+0]*G[3] + E[r2*4+1]*G[7] + E[r2*4+2]*G[11] + E[r2*4+3];
        }
        for (int i = 0; i < 12; i++) d_gpose[b*12 + i] = Ng[i];
    }
}

// ---------------- est_g ----------------
__global__ void estg_kernel() {
    int tid = threadIdx.x;
    if (tid < 8) {
        int b = tid;
        const float* g = d_gpose + b*12;
        const float* m0 = d_mean0 + b*3;
        const float* m1 = d_mean1 + b*3;
        float e[12];
        for (int r = 0; r < 3; r++) {
            e[r*4+0] = g[r*4+0]; e[r*4+1] = g[r*4+1]; e[r*4+2] = g[r*4+2];
            e[r*4+3] = -(g[r*4+0]*m1[0] + g[r*4+1]*m1[1] + g[r*4+2]*m1[2]) + g[r*4+3] + m0[r];
        }
        for (int i = 0; i < 12; i++) d_estg[b*12 + i] = e[i];
    }
}

// ---------------- loss ----------------
__global__ void loss_kernel(const float* __restrict__ p_src) {
    int bi = blockIdx.x;
    int b = bi >> 3, seg = bi & 7;
    int tid = threadIdx.x;
    int n = seg*256 + tid;
    const float* p = p_src + ((size_t)b*NN + n)*3;
    float x = p[0], y = p[1], z = p[2];
    const float* e = d_estg + b*12;
    const float* q = d_igtinv + b*12;
    float s = 0.f;
    #pragma unroll
    for (int r = 0; r < 3; r++) {
        float ae = e[r*4+0]*x + e[r*4+1]*y + e[r*4+2]*z + e[r*4+3];
        float aq = q[r*4+0]*x + q[r*4+1]*y + q[r*4+2]*z + q[r*4+3];
        s += fabsf(ae - aq);
    }
    __shared__ float sr[256];
    sr[tid] = s;
    __syncthreads();
    for (int st = 128; st; st >>= 1) {
        if (tid < st) sr[tid] += sr[tid + st];
        __syncthreads();
    }
    if (tid == 0) d_lpart[bi] = sr[0];
}

// ---------------- output ----------------
__global__ void finish_kernel(float* __restrict__ out, int out_size) {
    int i = blockIdx.x*256 + threadIdx.x;
    if (i < BB*KK && i < out_size) out[i] = d_r[i];
    if (blockIdx.x == 0 && threadIdx.x == 0 && out_size > BB*KK) {
        double s = 0.0;
        for (int j = 0; j < 64; j++) s += (double)d_lpart[j];
        out[BB*KK] = (float)(s / (double)(BB*NN*3));
    }
}

// ---------------- host ----------------
extern "C" void kernel_launch(void* const* d_in, const int* in_sizes, int n_in,
                              void* d_out, int out_size) {
    const float* p_src = (const float*)d_in[0];
    const float* p_tgt = (const float*)d_in[1];
    const float* igt   = (const float*)d_in[2];
    const float* dt    = (const float*)d_in[3];
    const float* W1    = (const float*)d_in[4];
    const float* b1    = (const float*)d_in[5];
    const float* W2    = (const float*)d_in[6];
    const float* b2    = (const float*)d_in[7];
    const float* W3    = (const float*)d_in[8];
    const float* b3    = (const float*)d_in[9];
    float* out = (float*)d_out;

    cudaFuncSetAttribute(encode_kernel<0>, cudaFuncAttributeMaxDynamicSharedMemorySize, ENC_SMEM_BYTES);
    cudaFuncSetAttribute(encode_kernel<1>, cudaFuncAttributeMaxDynamicSharedMemorySize, ENC_SMEM_BYTES);

    means_kernel<<<BB, 256>>>(p_tgt, p_src);
    setup_kernel<<<1, 32>>>(dt, igt);
    init_f_kernel<<<(BB*KK*2 + BB*6*KK + 255)/256, 256>>>();
    encode_kernel<0><<<dim3(NN/MP, BB*7), THREADS, ENC_SMEM_BYTES>>>(p_tgt, W1, b1, W2, b2, W3, b3);
    jh_kernel<<<BB, 256>>>(dt);
    for (int it = 0; it < 5; it++) {
        encode_kernel<1><<<dim3(NN/MP, BB), THREADS, ENC_SMEM_BYTES>>>(p_src, W1, b1, W2, b2, W3, b3);
        update_kernel<<<BB, 256>>>();
    }
    estg_kernel<<<1, 32>>>();
    loss_kernel<<<64, 256>>>(p_src);
    finish_kernel<<<(BB*KK + 256)/256 + 1, 256>>>(out, out_size);
}

// round 12
// speedup vs baseline: 1.3592x; 1.3592x over previous
#include <cuda_runtime.h>
#include <cuda_bf16.h>
#include <math.h>
#include <stdint.h>

#define BB 8
#define NN 2048
#define KK 1024
#define NP 64            // points per block

// ---------------- device state ----------------
__device__ float d_mean0[BB*3], d_mean1[BB*3];
__device__ float d_posesJ[7*12];
__device__ float d_gpose[BB*12];
__device__ float d_igtinv[BB*12];
__device__ float d_estg[BB*12];
__device__ float d_f0[BB*KK], d_fj[BB*6*KK], d_f1[BB*KK];
__device__ float d_J[BB*KK*6];
__device__ float d_Hinv[BB*36];
__device__ float d_r[BB*KK];
__device__ float d_lpart[64];

typedef unsigned long long u64;

// ---------------- helpers ----------------
__device__ __forceinline__ void atomicMaxF(float* addr, float val) {
    if (val >= 0.f) atomicMax((int*)addr, __float_as_int(val));
    else            atomicMin((unsigned int*)addr, __float_as_uint(val));
}
__device__ __forceinline__ u64 dup2(float a) {
    u64 r; asm("mov.b64 %0,{%1,%1};" : "=l"(r) : "f"(a)); return r;
}
__device__ __forceinline__ void unpk2(u64 v, float& a, float& b) {
    asm("mov.b64 {%0,%1},%2;" : "=f"(a), "=f"(b) : "l"(v));
}
__device__ __forceinline__ void fma2(u64& d, u64 a, u64 b) {
    asm("fma.rn.f32x2 %0,%1,%2,%0;" : "+l"(d) : "l"(a), "l"(b));
}
__device__ __forceinline__ void cp16(uint32_t dst, const void* src) {
    asm volatile("cp.async.cg.shared.global [%0], [%1], 16;\n" :: "r"(dst), "l"(src));
}
#define CP_COMMIT() asm volatile("cp.async.commit_group;\n" ::: "memory")

// se3_exp (double internals), output 3x4 row-major float
__device__ void se3_exp_d(const double w[3], const double v[3], float out[12]) {
    double t2 = w[0]*w[0] + w[1]*w[1] + w[2]*w[2];
    double t = sqrt(t2);
    double A, Bc, Cc;
    if (t < 1e-6) {
        A  = 1.0 - t2/6.0;  Bc = 0.5 - t2/24.0;  Cc = 1.0/6.0 - t2/120.0;
    } else {
        double st = sin(t), ct = cos(t);
        A = st/t;  Bc = (1.0-ct)/t2;  Cc = (t-st)/(t2*t);
    }
    double W[3][3] = {{0.0,-w[2],w[1]},{w[2],0.0,-w[0]},{-w[1],w[0],0.0}};
    double W2m[3][3];
    for (int i = 0; i < 3; i++)
        for (int j = 0; j < 3; j++)
            W2m[i][j] = w[i]*w[j] - (i==j ? t2 : 0.0);
    double R[3][3], V[3][3];
    for (int i = 0; i < 3; i++)
        for (int j = 0; j < 3; j++) {
            double I = (i==j) ? 1.0 : 0.0;
            R[i][j] = I + A*W[i][j] + Bc*W2m[i][j];
            V[i][j] = I + Bc*W[i][j] + Cc*W2m[i][j];
        }
    for (int i = 0; i < 3; i++) {
        double p = V[i][0]*v[0] + V[i][1]*v[1] + V[i][2]*v[2];
        out[i*4+0] = (float)R[i][0]; out[i*4+1] = (float)R[i][1];
        out[i*4+2] = (float)R[i][2]; out[i*4+3] = (float)p;
    }
}

// ---------------- means (blocks 0..7) + setup (block 8) ----------------
__global__ void prep_kernel(const float* __restrict__ p_tgt, const float* __restrict__ p_src,
                            const float* __restrict__ dt, const float* __restrict__ igt_twist) {
    int tid = threadIdx.x;
    if (blockIdx.x < 8) {
        int b = blockIdx.x;
        float a[6] = {0,0,0,0,0,0};
        for (int n = tid; n < NN; n += 256) {
            const float* pt = p_tgt + ((size_t)b*NN + n)*3;
            const float* ps = p_src + ((size_t)b*NN + n)*3;
            a[0] += pt[0]; a[1] += pt[1]; a[2] += pt[2];
            a[3] += ps[0]; a[4] += ps[1]; a[5] += ps[2];
        }
        for (int off = 16; off; off >>= 1)
            #pragma unroll
            for (int q = 0; q < 6; q++) a[q] += __shfl_down_sync(0xffffffffu, a[q], off);
        __shared__ float sm[8][6];
        int lane = tid & 31, w = tid >> 5;
        if (lane == 0) { for (int q = 0; q < 6; q++) sm[w][q] = a[q]; }
        __syncthreads();
        if (tid < 6) {
            float s = 0.f;
            for (int w2 = 0; w2 < 8; w2++) s += sm[w2][tid];
            s *= (1.0f / NN);
            if (tid < 3) d_mean0[b*3 + tid] = s;
            else         d_mean1[b*3 + tid - 3] = s;
        }
    } else {
        if (tid < 7) {
            float out[12];
            if (tid == 0) {
                float I[12] = {1,0,0,0, 0,1,0,0, 0,0,1,0};
                for (int i = 0; i < 12; i++) out[i] = I[i];
            } else {
                int j = tid - 1;
                double w[3] = {0,0,0}, v[3] = {0,0,0};
                double val = -(double)__ldg(&dt[j]);
                if (j < 3) w[j] = val; else v[j-3] = val;
                se3_exp_d(w, v, out);
            }
            for (int i = 0; i < 12; i++) d_posesJ[tid*12 + i] = out[i];
        }
        if (tid >= 8 && tid < 16) {
            int b = tid - 8;
            float I[12] = {1,0,0,0, 0,1,0,0, 0,0,1,0};
            for (int i = 0; i < 12; i++) d_gpose[b*12 + i] = I[i];
        }
        if (tid >= 16 && tid < 24) {
            int b = tid - 16;
            double w[3], v[3];
            for (int i = 0; i < 3; i++) { w[i] = igt_twist[b*6 + i]; v[i] = igt_twist[b*6 + 3 + i]; }
            float g[12];
            se3_exp_d(w, v, g);
            float inv[12];
            for (int r = 0; r < 3; r++)
                for (int c = 0; c < 3; c++) inv[r*4 + c] = g[c*4 + r];
            for (int r = 0; r < 3; r++)
                inv[r*4 + 3] = -(g[0*4+r]*g[3] + g[1*4+r]*g[7] + g[2*4+r]*g[11]);
            for (int i = 0; i < 12; i++) d_igtinv[b*12 + i] = inv[i];
        }
    }
}

// init f0, fj, f1 to -INF (once; update_kernel maintains f1 afterwards)
__global__ void init_f_kernel() {
    int i = blockIdx.x*256 + threadIdx.x;
    if (i < BB*KK) d_f0[i] = -INFINITY;
    else if (i < BB*KK + BB*6*KK) d_fj[i - BB*KK] = -INFINITY;
    else if (i < BB*KK + BB*6*KK + BB*KK) d_f1[i - BB*KK - BB*6*KK] = -INFINITY;
}

// ---------------- fused encode ----------------
// 256 threads, 64 points. K in 4 passes of 256 cols; each pass = 8 c-tiles
// (16 c x 256 k, 16KB). FOUR-deep cp.async ring, prefetch distance 3,
// ONE barrier per tile (writer of buf[(t+3)&3] is safe once all warps passed
// barrier t, since that buffer was last read at tile t-1).
// Thread micro-tile: 8p x 8k f32x2. Warp: 8 p-lanes x 4 k-lanes = 64p x 32k.
// H2T rows 64 floats (256B aligned); thread pl owns pts {4pl..4pl+3} U {32+4pl..}.
#define OFF_H2T  16384          /* 128 c x 64 = 8192 */
#define STRH2    64
#define SMEMF    24576
#define SMEM_BYTES (SMEMF*4)
// A-phase aliases: buffers 0-1 = [0,8192): pts/W1/b1/b2/H1; buffers 2-3 = [8192,16384): W2
#define OFF_PTS  0
#define OFF_SW1  192
#define OFF_SB1  384
#define OFF_SB2  448
#define OFF_H1   576            /* 64 x 68 -> ends 4928 < 8192 */
#define OFF_W2   8192

// Stage tile t (t = kp*8 + ct): rows c = ct*16..+15, cols k = kp*256..+255.
__device__ __forceinline__ void issue_tile(uint32_t sbase, int t,
                                           const float* __restrict__ W3g, int tid) {
    uint32_t buf = sbase + (uint32_t)(t & 3) * (4096u * 4u);
    int kp = t >> 3, ct = t & 7;
    const float* src = W3g + (size_t)(ct*16)*1024 + kp*256;
    #pragma unroll
    for (int i = 0; i < 4; i++) {
        int f4 = i*256 + tid;              // 1024 float4 total (16 rows x 64)
        int row = f4 >> 6, col4 = f4 & 63;
        cp16(buf + (uint32_t)(row*256 + col4*4)*4u, src + (size_t)row*1024 + col4*4);
    }
}

template<int MODE>
__global__ __launch_bounds__(256, 2)
void encode_kernel(const float* __restrict__ P,
                   const float* __restrict__ W1g, const float* __restrict__ b1g,
                   const float* __restrict__ W2g, const float* __restrict__ b2g,
                   const float* __restrict__ W3g, const float* __restrict__ b3g) {
    extern __shared__ float sm[];
    int tid = threadIdx.x;
    uint32_t sbase = (uint32_t)__cvta_generic_to_shared(sm);

    int b; const float* pose; const float* mean; float* out;
    if (MODE == 0) {
        int bm = blockIdx.y;
        b = bm / 7; int m = bm % 7;
        pose = d_posesJ + m*12;
        mean = d_mean0 + b*3;
        out  = (m == 0) ? (d_f0 + b*KK) : (d_fj + ((size_t)b*6 + (m-1))*KK);
    } else {
        b = blockIdx.y;
        pose = d_gpose + b*12;
        mean = d_mean1 + b*3;
        out  = d_f1 + b*KK;
    }

    // phase A0: stage weights + transform points
    {
        const float4* w2v = (const float4*)W2g;
        #pragma unroll
        for (int i = 0; i < 8; i++)
            *(float4*)&sm[OFF_W2 + (tid + i*256)*4] = w2v[tid + i*256];
    }
    if (tid >= 64 && tid < 256) sm[OFF_SW1 + tid - 64] = W1g[tid - 64];
    if (tid < 64)  sm[OFF_SB1 + tid] = b1g[tid];
    if (tid >= 64 && tid < 192) sm[OFF_SB2 + tid - 64] = b2g[tid - 64];
    if (tid < NP) {
        int n = blockIdx.x * NP + tid;
        const float* pp = P + ((size_t)b*NN + n)*3;
        float dx = pp[0] - mean[0], dy = pp[1] - mean[1], dz = pp[2] - mean[2];
        sm[OFF_PTS + tid*3 + 0] = pose[0]*dx + pose[1]*dy + pose[2]*dz  + pose[3];
        sm[OFF_PTS + tid*3 + 1] = pose[4]*dx + pose[5]*dy + pose[6]*dz  + pose[7];
        sm[OFF_PTS + tid*3 + 2] = pose[8]*dx + pose[9]*dy + pose[10]*dz + pose[11];
    }
    __syncthreads();

    // phase A1: h1 = relu(pt @ W1 + b1), 64 x 64 (stride 68)
    #pragma unroll
    for (int i = 0; i < 16; i++) {
        int idx = tid + i*256;
        int p = idx >> 6, c1 = idx & 63;
        float x = sm[OFF_PTS + p*3 + 0], y = sm[OFF_PTS + p*3 + 1], z = sm[OFF_PTS + p*3 + 2];
        float v = sm[OFF_SB1 + c1];
        v = fmaf(x, sm[OFF_SW1 + c1],       v);
        v = fmaf(y, sm[OFF_SW1 + 64 + c1],  v);
        v = fmaf(z, sm[OFF_SW1 + 128 + c1], v);
        sm[OFF_H1 + p*68 + c1] = fmaxf(v, 0.f);
    }
    __syncthreads();

    // phase A2: h2T[c2][p] = relu(h1[p] @ W2[:,c2] + b2), rows 64 floats
    {
        int p = tid >> 2, r = tid & 3;
        float hr[64];
        #pragma unroll
        for (int i = 0; i < 16; i++) {
            float4 h4 = *(const float4*)&sm[OFF_H1 + p*68 + i*4];
            hr[i*4+0] = h4.x; hr[i*4+1] = h4.y; hr[i*4+2] = h4.z; hr[i*4+3] = h4.w;
        }
        #pragma unroll
        for (int q = 0; q < 8; q++) {
            int c2 = r*4 + q*16;
            float4 acc = *(const float4*)&sm[OFF_SB2 + c2];
            #pragma unroll 16
            for (int c1 = 0; c1 < 64; c1++) {
                float4 w = *(const float4*)&sm[OFF_W2 + c1*128 + c2];
                float h = hr[c1];
                acc.x = fmaf(h, w.x, acc.x); acc.y = fmaf(h, w.y, acc.y);
                acc.z = fmaf(h, w.z, acc.z); acc.w = fmaf(h, w.w, acc.w);
            }
            sm[OFF_H2T + (c2+0)*STRH2 + p] = fmaxf(acc.x, 0.f);
            sm[OFF_H2T + (c2+1)*STRH2 + p] = fmaxf(acc.y, 0.f);
            sm[OFF_H2T + (c2+2)*STRH2 + p] = fmaxf(acc.z, 0.f);
            sm[OFF_H2T + (c2+3)*STRH2 + p] = fmaxf(acc.w, 0.f);
        }
    }
    __syncthreads();   // W3 ring region now free

    issue_tile(sbase, 0, W3g, tid); CP_COMMIT();
    issue_tile(sbase, 1, W3g, tid); CP_COMMIT();
    issue_tile(sbase, 2, W3g, tid); CP_COMMIT();

    // phase B: 32 tiles (4 k-passes x 8 c-tiles of 16 c), 1 barrier per tile
    int lane = tid & 31, w = tid >> 5;
    int pl = lane & 7, kl = lane >> 3;
    const float* hbase = &sm[OFF_H2T + pl*4];
    u64 acc[4][8];                              // [p-pair][k]

    for (int t = 0; t < 32; t++) {
        int kp = t >> 3, ct = t & 7;
        if (t < 30)      asm volatile("cp.async.wait_group 2;\n" ::: "memory");
        else if (t == 30) asm volatile("cp.async.wait_group 1;\n" ::: "memory");
        else             asm volatile("cp.async.wait_group 0;\n" ::: "memory");
        __syncthreads();   // tile t data visible to all; buf[(t+3)&3] free

        if (t + 3 < 32) { issue_tile(sbase, t + 3, W3g, tid); CP_COMMIT(); }

        if (ct == 0) {
            #pragma unroll
            for (int i = 0; i < 4; i++)
                #pragma unroll
                for (int j = 0; j < 8; j++) acc[i][j] = 0ull;
        }

        const float* wbase = &sm[(t & 3)*4096] + w*32 + kl*8;
        const float* hrow = hbase + (ct*16)*STRH2;

        #pragma unroll 4
        for (int c = 0; c < 16; c++) {
            ulonglong2 hA = *(const ulonglong2*)&hrow[c*STRH2];        // pts 4pl..+3
            ulonglong2 hB = *(const ulonglong2*)&hrow[c*STRH2 + 32];   // pts 32+4pl..+3
            float4 wa = *(const float4*)&wbase[c*256];
            float4 wb = *(const float4*)&wbase[c*256 + 4];
            u64 wd;
            wd = dup2(wa.x);
            fma2(acc[0][0], hA.x, wd); fma2(acc[1][0], hA.y, wd);
            fma2(acc[2][0], hB.x, wd); fma2(acc[3][0], hB.y, wd);
            wd = dup2(wa.y);
            fma2(acc[0][1], hA.x, wd); fma2(acc[1][1], hA.y, wd);
            fma2(acc[2][1], hB.x, wd); fma2(acc[3][1], hB.y, wd);
            wd = dup2(wa.z);
            fma2(acc[0][2], hA.x, wd); fma2(acc[1][2], hA.y, wd);
            fma2(acc[2][2], hB.x, wd); fma2(acc[3][2], hB.y, wd);
            wd = dup2(wa.w);
            fma2(acc[0][3], hA.x, wd); fma2(acc[1][3], hA.y, wd);
            fma2(acc[2][3], hB.x, wd); fma2(acc[3][3], hB.y, wd);
            wd = dup2(wb.x);
            fma2(acc[0][4], hA.x, wd); fma2(acc[1][4], hA.y, wd);
            fma2(acc[2][4], hB.x, wd); fma2(acc[3][4], hB.y, wd);
            wd = dup2(wb.y);
            fma2(acc[0][5], hA.x, wd); fma2(acc[1][5], hA.y, wd);
            fma2(acc[2][5], hB.x, wd); fma2(acc[3][5], hB.y, wd);
            wd = dup2(wb.z);
            fma2(acc[0][6], hA.x, wd); fma2(acc[1][6], hA.y, wd);
            fma2(acc[2][6], hB.x, wd); fma2(acc[3][6], hB.y, wd);
            wd = dup2(wb.w);
            fma2(acc[0][7], hA.x, wd); fma2(acc[1][7], hA.y, wd);
            fma2(acc[2][7], hB.x, wd); fma2(acc[3][7], hB.y, wd);
        }

        if (ct == 7) {
            // max over this thread's 8 points -> mx[k], then over 8 p-lanes
            float mx[8];
            #pragma unroll
            for (int j = 0; j < 8; j++) {
                float a0, b0, a1, b1, a2, b2, a3, b3;
                unpk2(acc[0][j], a0, b0); unpk2(acc[1][j], a1, b1);
                unpk2(acc[2][j], a2, b2); unpk2(acc[3][j], a3, b3);
                mx[j] = fmaxf(fmaxf(fmaxf(a0, b0), fmaxf(a1, b1)),
                              fmaxf(fmaxf(a2, b2), fmaxf(a3, b3)));
            }
            #pragma unroll
            for (int off = 1; off < 8; off <<= 1)
                #pragma unroll
                for (int j = 0; j < 8; j++)
                    mx[j] = fmaxf(mx[j], __shfl_xor_sync(0xffffffffu, mx[j], off));
            int k = kp*256 + w*32 + kl*8 + pl;
            atomicMaxF(&out[k], mx[pl] + __ldg(&b3g[k]));
        }
    }
}

// ---------------- J and Hinv ----------------
__global__ void jh_kernel(const float* __restrict__ dt) {
    int b = blockIdx.x, tid = threadIdx.x;
    float dtv[6];
    #pragma unroll
    for (int j = 0; j < 6; j++) dtv[j] = __ldg(&dt[j]);
    double hacc[21];
    #pragma unroll
    for (int q = 0; q < 21; q++) hacc[q] = 0.0;
    for (int k = tid; k < KK; k += 256) {
        float f0k = d_f0[b*KK + k];
        float jv[6];
        #pragma unroll
        for (int j = 0; j < 6; j++) {
            jv[j] = (f0k - d_fj[((size_t)b*6 + j)*KK + k]) / dtv[j];
            d_J[((size_t)b*KK + k)*6 + j] = jv[j];
        }
        int q = 0;
        #pragma unroll
        for (int i = 0; i < 6; i++)
            #pragma unroll
            for (int j = i; j < 6; j++)
                hacc[q++] += (double)jv[i] * (double)jv[j];
    }
    for (int off = 16; off; off >>= 1)
        #pragma unroll
        for (int q = 0; q < 21; q++) hacc[q] += __shfl_down_sync(0xffffffffu, hacc[q], off);
    __shared__ double shH[8][21];
    int lane = tid & 31, w = tid >> 5;
    if (lane == 0) { for (int q = 0; q < 21; q++) shH[w][q] = hacc[q]; }
    __syncthreads();
    if (tid == 0) {
        double s[21];
        for (int q = 0; q < 21; q++) { s[q] = 0.0; for (int w2 = 0; w2 < 8; w2++) s[q] += shH[w2][q]; }
        double H[6][6];
        int q = 0;
        for (int i = 0; i < 6; i++)
            for (int j = i; j < 6; j++) { H[i][j] = s[q]; H[j][i] = s[q]; q++; }
        double M[6][12];
        for (int i = 0; i < 6; i++)
            for (int j = 0; j < 12; j++) M[i][j] = (j < 6) ? H[i][j] : ((j - 6 == i) ? 1.0 : 0.0);
        for (int col = 0; col < 6; col++) {
            int piv = col; double best = fabs(M[col][col]);
            for (int r2 = col + 1; r2 < 6; r2++)
                if (fabs(M[r2][col]) > best) { best = fabs(M[r2][col]); piv = r2; }
            if (piv != col)
                for (int j = 0; j < 12; j++) { double t = M[col][j]; M[col][j] = M[piv][j]; M[piv][j] = t; }
            double inv = 1.0 / M[col][col];
            for (int j = 0; j < 12; j++) M[col][j] *= inv;
            for (int r2 = 0; r2 < 6; r2++) {
                if (r2 == col) continue;
                double f = M[r2][col];
                for (int j = 0; j < 12; j++) M[r2][j] -= f * M[col][j];
            }
        }
        for (int i = 0; i < 6; i++)
            for (int j = 0; j < 6; j++) d_Hinv[b*36 + i*6 + j] = (float)M[i][6 + j];
    }
}

// ---------------- Gauss-Newton update (also resets f1 for next iter) ----------------
__global__ void update_kernel() {
    int b = blockIdx.x, tid = threadIdx.x;
    double u[6] = {0,0,0,0,0,0};
    for (int k = tid; k < KK; k += 256) {
        float r = d_f1[b*KK + k] - d_f0[b*KK + k];
        d_r[b*KK + k] = r;
        d_f1[b*KK + k] = -INFINITY;
        #pragma unroll
        for (int j = 0; j < 6; j++) u[j] += (double)d_J[((size_t)b*KK + k)*6 + j] * (double)r;
    }
    for (int off = 16; off; off >>= 1)
        #pragma unroll
        for (int j = 0; j < 6; j++) u[j] += __shfl_down_sync(0xffffffffu, u[j], off);
    __shared__ double shU[8][6];
    int lane = tid & 31, w = tid >> 5;
    if (lane == 0) { for (int j = 0; j < 6; j++) shU[w][j] = u[j]; }
    __syncthreads();
    if (tid == 0) {
        double uu[6];
        for (int j = 0; j < 6; j++) { uu[j] = 0.0; for (int w2 = 0; w2 < 8; w2++) uu[j] += shU[w2][j]; }
        double dx[6];
        for (int i = 0; i < 6; i++) {
            double s2 = 0.0;
            for (int j = 0; j < 6; j++) s2 += (double)d_Hinv[b*36 + i*6 + j] * uu[j];
            dx[i] = -s2;
        }
        float E[12];
        double wv[3] = {dx[0], dx[1], dx[2]}, vv[3] = {dx[3], dx[4], dx[5]};
        se3_exp_d(wv, vv, E);
        float G[12];
        for (int i = 0; i < 12; i++) G[i] = d_gpose[b*12 + i];
        float Ng[12];
        for (int r2 = 0; r2 < 3; r2++) {
            for (int c = 0; c < 3; c++)
                Ng[r2*4 + c] = E[r2*4+0]*G[0*4+c] + E[r2*4+1]*G[1*4+c] + E[r2*4+2]*G[2*4+c];
            Ng[r2*4 + 3] = E[r2*4+0]*G[3] + E[r2*4+1]*G[7] + E[r2*4+2]*G[11] + E[r2*4+3];
        }
        for (int i = 0; i < 12; i++) d_gpose[b*12 + i] = Ng[i];
    }
}

// ---------------- est_g ----------------
__global__ void estg_kernel() {
    int tid = threadIdx.x;
    if (tid < 8) {
        int b = tid;
        const float* g = d_gpose + b*12;
        const float* m0 = d_mean0 + b*3;
        const float* m1 = d_mean1 + b*3;
        float e[12];
        for (int r = 0; r < 3; r++) {
            e[r*4+0] = g[r*4+0]; e[r*4+1] = g[r*4+1]; e[r*4+2] = g[r*4+2];
            e[r*4+3] = -(g[r*4+0]*m1[0] + g[r*4+1]*m1[1] + g[r*4+2]*m1[2]) + g[r*4+3] + m0[r];
        }
        for (int i = 0; i < 12; i++) d_estg[b*12 + i] = e[i];
    }
}

// ---------------- loss ----------------
__global__ void loss_kernel(const float* __restrict__ p_src) {
    int bi = blockIdx.x;
    int b = bi >> 3, seg = bi & 7;
    int tid = threadIdx.x;
    int n = seg*256 + tid;
    const float* p = p_src + ((size_t)b*NN + n)*3;
    float x = p[0], y = p[1], z = p[2];
    const float* e = d_estg + b*12;
    const float* q = d_igtinv + b*12;
    float s = 0.f;
    #pragma unroll
    for (int r = 0; r < 3; r++) {
        float ae = e[r*4+0]*x + e[r*4+1]*y + e[r*4+2]*z + e[r*4+3];
        float aq = q[r*4+0]*x + q[r*4+1]*y + q[r*4+2]*z + q[r*4+3];
        s += fabsf(ae - aq);
    }
    __shared__ float sr[256];
    sr[tid] = s;
    __syncthreads();
    for (int st = 128; st; st >>= 1) {
        if (tid < st) sr[tid] += sr[tid + st];
        __syncthreads();
    }
    if (tid == 0) d_lpart[bi] = sr[0];
}

// ---------------- output ----------------
__global__ void finish_kernel(float* __restrict__ out, int out_size) {
    int i = blockIdx.x*256 + threadIdx.x;
    if (i < BB*KK && i < out_size) out[i] = d_r[i];
    if (blockIdx.x == 0 && threadIdx.x == 0 && out_size > BB*KK) {
        double s = 0.0;
        for (int j = 0; j < 64; j++) s += (double)d_lpart[j];
        out[BB*KK] = (float)(s / (double)(BB*NN*3));
    }
}

// ---------------- host ----------------
extern "C" void kernel_launch(void* const* d_in, const int* in_sizes, int n_in,
                              void* d_out, int out_size) {
    const float* p_src = (const float*)d_in[0];
    const float* p_tgt = (const float*)d_in[1];
    const float* igt   = (const float*)d_in[2];
    const float* dt    = (const float*)d_in[3];
    const float* W1    = (const float*)d_in[4];
    const float* b1    = (const float*)d_in[5];
    const float* W2    = (const float*)d_in[6];
    const float* b2    = (const float*)d_in[7];
    const float* W3    = (const float*)d_in[8];
    const float* b3    = (const float*)d_in[9];
    float* out = (float*)d_out;

    cudaFuncSetAttribute(encode_kernel<0>, cudaFuncAttributeMaxDynamicSharedMemorySize, SMEM_BYTES);
    cudaFuncSetAttribute(encode_kernel<1>, cudaFuncAttributeMaxDynamicSharedMemorySize, SMEM_BYTES);

    prep_kernel<<<9, 256>>>(p_tgt, p_src, dt, igt);
    init_f_kernel<<<(BB*KK*2 + BB*6*KK + 255)/256, 256>>>();
    encode_kernel<0><<<dim3(NN/NP, BB*7), 256, SMEM_BYTES>>>(p_tgt, W1, b1, W2, b2, W3, b3);
    jh_kernel<<<BB, 256>>>(dt);
    for (int it = 0; it < 5; it++) {
        encode_kernel<1><<<dim3(NN/NP, BB), 256, SMEM_BYTES>>>(p_src, W1, b1, W2, b2, W3, b3);
        update_kernel<<<BB, 256>>>();
    }
    estg_kernel<<<1, 32>>>();
    loss_kernel<<<64, 256>>>(p_src);
    finish_kernel<<<(BB*KK + 256)/256 + 1, 256>>>(out, out_size);
}

// round 13
// speedup vs baseline: 1.4537x; 1.0695x over previous
#include <cuda_runtime.h>
#include <cuda_bf16.h>
#include <math.h>
#include <stdint.h>

#define BB 8
#define NN 2048
#define KK 1024
#define NP 64            // points per block

// ---------------- device state ----------------
__device__ float d_mean0[BB*3], d_mean1[BB*3];
__device__ float d_posesJ[7*12];
__device__ float d_gpose[BB*12];
__device__ float d_igtinv[BB*12];
__device__ float d_estg[BB*12];
__device__ float d_f0[BB*KK], d_fj[BB*6*KK], d_f1[BB*KK];
__device__ float d_J[BB*KK*6];
__device__ float d_Hinv[BB*36];
__device__ float d_r[BB*KK];
__device__ float d_lpart[64];

typedef unsigned long long u64;

// ---------------- helpers ----------------
__device__ __forceinline__ void atomicMaxF(float* addr, float val) {
    if (val >= 0.f) atomicMax((int*)addr, __float_as_int(val));
    else            atomicMin((unsigned int*)addr, __float_as_uint(val));
}
__device__ __forceinline__ u64 dup2(float a) {
    u64 r; asm("mov.b64 %0,{%1,%1};" : "=l"(r) : "f"(a)); return r;
}
__device__ __forceinline__ u64 pk2(float a, float b) {
    u64 r; asm("mov.b64 %0,{%1,%2};" : "=l"(r) : "f"(a), "f"(b)); return r;
}
__device__ __forceinline__ void unpk2(u64 v, float& a, float& b) {
    asm("mov.b64 {%0,%1},%2;" : "=f"(a), "=f"(b) : "l"(v));
}
__device__ __forceinline__ void fma2(u64& d, u64 a, u64 b) {
    asm("fma.rn.f32x2 %0,%1,%2,%0;" : "+l"(d) : "l"(a), "l"(b));
}
__device__ __forceinline__ void cp16(uint32_t dst, const void* src) {
    asm volatile("cp.async.cg.shared.global [%0], [%1], 16;\n" :: "r"(dst), "l"(src));
}
#define CP_COMMIT() asm volatile("cp.async.commit_group;\n" ::: "memory")

// se3_exp (double internals), output 3x4 row-major float
__device__ void se3_exp_d(const double w[3], const double v[3], float out[12]) {
    double t2 = w[0]*w[0] + w[1]*w[1] + w[2]*w[2];
    double t = sqrt(t2);
    double A, Bc, Cc;
    if (t < 1e-6) {
        A  = 1.0 - t2/6.0;  Bc = 0.5 - t2/24.0;  Cc = 1.0/6.0 - t2/120.0;
    } else {
        double st = sin(t), ct = cos(t);
        A = st/t;  Bc = (1.0-ct)/t2;  Cc = (t-st)/(t2*t);
    }
    double W[3][3] = {{0.0,-w[2],w[1]},{w[2],0.0,-w[0]},{-w[1],w[0],0.0}};
    double W2m[3][3];
    for (int i = 0; i < 3; i++)
        for (int j = 0; j < 3; j++)
            W2m[i][j] = w[i]*w[j] - (i==j ? t2 : 0.0);
    double R[3][3], V[3][3];
    for (int i = 0; i < 3; i++)
        for (int j = 0; j < 3; j++) {
            double I = (i==j) ? 1.0 : 0.0;
            R[i][j] = I + A*W[i][j] + Bc*W2m[i][j];
            V[i][j] = I + Bc*W[i][j] + Cc*W2m[i][j];
        }
    for (int i = 0; i < 3; i++) {
        double p = V[i][0]*v[0] + V[i][1]*v[1] + V[i][2]*v[2];
        out[i*4+0] = (float)R[i][0]; out[i*4+1] = (float)R[i][1];
        out[i*4+2] = (float)R[i][2]; out[i*4+3] = (float)p;
    }
}

// ---------------- means (blocks 0..7) + setup (block 8) ----------------
__global__ void prep_kernel(const float* __restrict__ p_tgt, const float* __restrict__ p_src,
                            const float* __restrict__ dt, const float* __restrict__ igt_twist) {
    int tid = threadIdx.x;
    if (blockIdx.x < 8) {
        int b = blockIdx.x;
        float a[6] = {0,0,0,0,0,0};
        for (int n = tid; n < NN; n += 256) {
            const float* pt = p_tgt + ((size_t)b*NN + n)*3;
            const float* ps = p_src + ((size_t)b*NN + n)*3;
            a[0] += pt[0]; a[1] += pt[1]; a[2] += pt[2];
            a[3] += ps[0]; a[4] += ps[1]; a[5] += ps[2];
        }
        for (int off = 16; off; off >>= 1)
            #pragma unroll
            for (int q = 0; q < 6; q++) a[q] += __shfl_down_sync(0xffffffffu, a[q], off);
        __shared__ float sm[8][6];
        int lane = tid & 31, w = tid >> 5;
        if (lane == 0) { for (int q = 0; q < 6; q++) sm[w][q] = a[q]; }
        __syncthreads();
        if (tid < 6) {
            float s = 0.f;
            for (int w2 = 0; w2 < 8; w2++) s += sm[w2][tid];
            s *= (1.0f / NN);
            if (tid < 3) d_mean0[b*3 + tid] = s;
            else         d_mean1[b*3 + tid - 3] = s;
        }
    } else {
        if (tid < 7) {
            float out[12];
            if (tid == 0) {
                float I[12] = {1,0,0,0, 0,1,0,0, 0,0,1,0};
                for (int i = 0; i < 12; i++) out[i] = I[i];
            } else {
                int j = tid - 1;
                double w[3] = {0,0,0}, v[3] = {0,0,0};
                double val = -(double)__ldg(&dt[j]);
                if (j < 3) w[j] = val; else v[j-3] = val;
                se3_exp_d(w, v, out);
            }
            for (int i = 0; i < 12; i++) d_posesJ[tid*12 + i] = out[i];
        }
        if (tid >= 8 && tid < 16) {
            int b = tid - 8;
            float I[12] = {1,0,0,0, 0,1,0,0, 0,0,1,0};
            for (int i = 0; i < 12; i++) d_gpose[b*12 + i] = I[i];
        }
        if (tid >= 16 && tid < 24) {
            int b = tid - 16;
            double w[3], v[3];
            for (int i = 0; i < 3; i++) { w[i] = igt_twist[b*6 + i]; v[i] = igt_twist[b*6 + 3 + i]; }
            float g[12];
            se3_exp_d(w, v, g);
            float inv[12];
            for (int r = 0; r < 3; r++)
                for (int c = 0; c < 3; c++) inv[r*4 + c] = g[c*4 + r];
            for (int r = 0; r < 3; r++)
                inv[r*4 + 3] = -(g[0*4+r]*g[3] + g[1*4+r]*g[7] + g[2*4+r]*g[11]);
            for (int i = 0; i < 12; i++) d_igtinv[b*12 + i] = inv[i];
        }
    }
}

// init f0, fj, f1 to -INF (once; update_kernel maintains f1 afterwards)
__global__ void init_f_kernel() {
    int i = blockIdx.x*256 + threadIdx.x;
    if (i < BB*KK) d_f0[i] = -INFINITY;
    else if (i < BB*KK + BB*6*KK) d_fj[i - BB*KK] = -INFINITY;
    else if (i < BB*KK + BB*6*KK + BB*KK) d_f1[i - BB*KK - BB*6*KK] = -INFINITY;
}

// ---------------- fused encode ----------------
// 256 threads, 64 points. K in 4 passes of 256 cols; each pass = 8 c-tiles
// (16 c x 256 k, 16KB). FOUR-deep cp.async ring, prefetch distance 3,
// ONE barrier per tile. Thread micro-tile: 8p x 8k f32x2.
// Warp: 8 p-lanes x 4 k-lanes = 64p x 32k.
#define OFF_H2T  16384          /* 128 c x 64 = 8192 */
#define STRH2    64
#define SMEMF    24576
#define SMEM_BYTES (SMEMF*4)
// A-phase aliases: buffers 0-1 = [0,8192): pts/W1/b1/b2/H1; buffers 2-3 = [8192,16384): W2
#define OFF_PTS  0
#define OFF_SW1  192
#define OFF_SB1  384
#define OFF_SB2  448
#define OFF_H1   576            /* 64 x 68 -> ends 4928 < 8192 */
#define OFF_W2   8192

// Stage tile t (t = kp*8 + ct): rows c = ct*16..+15, cols k = kp*256..+255.
__device__ __forceinline__ void issue_tile(uint32_t sbase, int t,
                                           const float* __restrict__ W3g, int tid) {
    uint32_t buf = sbase + (uint32_t)(t & 3) * (4096u * 4u);
    int kp = t >> 3, ct = t & 7;
    const float* src = W3g + (size_t)(ct*16)*1024 + kp*256;
    #pragma unroll
    for (int i = 0; i < 4; i++) {
        int f4 = i*256 + tid;              // 1024 float4 total (16 rows x 64)
        int row = f4 >> 6, col4 = f4 & 63;
        cp16(buf + (uint32_t)(row*256 + col4*4)*4u, src + (size_t)row*1024 + col4*4);
    }
}

template<int MODE>
__global__ __launch_bounds__(256, 2)
void encode_kernel(const float* __restrict__ P,
                   const float* __restrict__ W1g, const float* __restrict__ b1g,
                   const float* __restrict__ W2g, const float* __restrict__ b2g,
                   const float* __restrict__ W3g, const float* __restrict__ b3g) {
    extern __shared__ float sm[];
    int tid = threadIdx.x;
    uint32_t sbase = (uint32_t)__cvta_generic_to_shared(sm);

    int b; const float* pose; const float* mean; float* out;
    if (MODE == 0) {
        int bm = blockIdx.y;
        b = bm / 7; int m = bm % 7;
        pose = d_posesJ + m*12;
        mean = d_mean0 + b*3;
        out  = (m == 0) ? (d_f0 + b*KK) : (d_fj + ((size_t)b*6 + (m-1))*KK);
    } else {
        b = blockIdx.y;
        pose = d_gpose + b*12;
        mean = d_mean1 + b*3;
        out  = d_f1 + b*KK;
    }

    // phase A0: stage weights + transform points
    {
        const float4* w2v = (const float4*)W2g;
        #pragma unroll
        for (int i = 0; i < 8; i++)
            *(float4*)&sm[OFF_W2 + (tid + i*256)*4] = w2v[tid + i*256];
    }
    if (tid >= 64 && tid < 256) sm[OFF_SW1 + tid - 64] = W1g[tid - 64];
    if (tid < 64)  sm[OFF_SB1 + tid] = b1g[tid];
    if (tid >= 64 && tid < 192) sm[OFF_SB2 + tid - 64] = b2g[tid - 64];
    if (tid < NP) {
        int n = blockIdx.x * NP + tid;
        const float* pp = P + ((size_t)b*NN + n)*3;
        float dx = pp[0] - mean[0], dy = pp[1] - mean[1], dz = pp[2] - mean[2];
        sm[OFF_PTS + tid*3 + 0] = pose[0]*dx + pose[1]*dy + pose[2]*dz  + pose[3];
        sm[OFF_PTS + tid*3 + 1] = pose[4]*dx + pose[5]*dy + pose[6]*dz  + pose[7];
        sm[OFF_PTS + tid*3 + 2] = pose[8]*dx + pose[9]*dy + pose[10]*dz + pose[11];
    }
    __syncthreads();

    // phase A1: h1 = relu(pt @ W1 + b1), 64 x 64 (stride 68)
    #pragma unroll
    for (int i = 0; i < 16; i++) {
        int idx = tid + i*256;
        int p = idx >> 6, c1 = idx & 63;
        float x = sm[OFF_PTS + p*3 + 0], y = sm[OFF_PTS + p*3 + 1], z = sm[OFF_PTS + p*3 + 2];
        float v = sm[OFF_SB1 + c1];
        v = fmaf(x, sm[OFF_SW1 + c1],       v);
        v = fmaf(y, sm[OFF_SW1 + 64 + c1],  v);
        v = fmaf(z, sm[OFF_SW1 + 128 + c1], v);
        sm[OFF_H1 + p*68 + c1] = fmaxf(v, 0.f);
    }
    __syncthreads();

    // phase A2: h2T[c2][p] = relu(h1[p] @ W2[:,c2] + b2), f32x2 accumulation
    {
        int p = tid >> 2, r = tid & 3;
        u64 acc2[16];
        #pragma unroll
        for (int q = 0; q < 8; q++) {
            int c2 = r*4 + q*16;
            acc2[q*2+0] = pk2(sm[OFF_SB2 + c2],     sm[OFF_SB2 + c2 + 1]);
            acc2[q*2+1] = pk2(sm[OFF_SB2 + c2 + 2], sm[OFF_SB2 + c2 + 3]);
        }
        #pragma unroll
        for (int half = 0; half < 2; half++) {
            float hr[32];
            #pragma unroll
            for (int i = 0; i < 8; i++) {
                float4 h4 = *(const float4*)&sm[OFF_H1 + p*68 + half*32 + i*4];
                hr[i*4+0] = h4.x; hr[i*4+1] = h4.y; hr[i*4+2] = h4.z; hr[i*4+3] = h4.w;
            }
            #pragma unroll 8
            for (int c1i = 0; c1i < 32; c1i++) {
                int c1 = half*32 + c1i;
                u64 hd = dup2(hr[c1i]);
                #pragma unroll
                for (int q = 0; q < 8; q++) {
                    int c2 = r*4 + q*16;
                    ulonglong2 w2 = *(const ulonglong2*)&sm[OFF_W2 + c1*128 + c2];
                    fma2(acc2[q*2+0], hd, w2.x);
                    fma2(acc2[q*2+1], hd, w2.y);
                }
            }
        }
        #pragma unroll
        for (int q = 0; q < 8; q++) {
            int c2 = r*4 + q*16;
            float v0, v1, v2, v3;
            unpk2(acc2[q*2+0], v0, v1);
            unpk2(acc2[q*2+1], v2, v3);
            sm[OFF_H2T + (c2+0)*STRH2 + p] = fmaxf(v0, 0.f);
            sm[OFF_H2T + (c2+1)*STRH2 + p] = fmaxf(v1, 0.f);
            sm[OFF_H2T + (c2+2)*STRH2 + p] = fmaxf(v2, 0.f);
            sm[OFF_H2T + (c2+3)*STRH2 + p] = fmaxf(v3, 0.f);
        }
    }
    __syncthreads();   // W3 ring region now free

    issue_tile(sbase, 0, W3g, tid); CP_COMMIT();
    issue_tile(sbase, 1, W3g, tid); CP_COMMIT();
    issue_tile(sbase, 2, W3g, tid); CP_COMMIT();

    // phase B: 32 tiles (4 k-passes x 8 c-tiles of 16 c), 1 barrier per tile
    int lane = tid & 31, w = tid >> 5;
    int pl = lane & 7, kl = lane >> 3;
    const float* hbase = &sm[OFF_H2T + pl*4];
    u64 acc[4][8];                              // [p-pair][k]

    for (int t = 0; t < 32; t++) {
        int kp = t >> 3, ct = t & 7;
        if (t < 30)       asm volatile("cp.async.wait_group 2;\n" ::: "memory");
        else if (t == 30) asm volatile("cp.async.wait_group 1;\n" ::: "memory");
        else              asm volatile("cp.async.wait_group 0;\n" ::: "memory");
        __syncthreads();   // tile t data visible; buf[(t+3)&3] free

        if (t + 3 < 32) { issue_tile(sbase, t + 3, W3g, tid); CP_COMMIT(); }

        if (ct == 0) {
            #pragma unroll
            for (int i = 0; i < 4; i++)
                #pragma unroll
                for (int j = 0; j < 8; j++) acc[i][j] = 0ull;
        }

        const float* wbase = &sm[(t & 3)*4096] + w*32 + kl*8;
        const float* hrow = hbase + (ct*16)*STRH2;

        #pragma unroll 4
        for (int c = 0; c < 16; c++) {
            ulonglong2 hA = *(const ulonglong2*)&hrow[c*STRH2];        // pts 4pl..+3
            ulonglong2 hB = *(const ulonglong2*)&hrow[c*STRH2 + 32];   // pts 32+4pl..+3
            float4 wa = *(const float4*)&wbase[c*256];
            float4 wb = *(const float4*)&wbase[c*256 + 4];
            u64 wd;
            wd = dup2(wa.x);
            fma2(acc[0][0], hA.x, wd); fma2(acc[1][0], hA.y, wd);
            fma2(acc[2][0], hB.x, wd); fma2(acc[3][0], hB.y, wd);
            wd = dup2(wa.y);
            fma2(acc[0][1], hA.x, wd); fma2(acc[1][1], hA.y, wd);
            fma2(acc[2][1], hB.x, wd); fma2(acc[3][1], hB.y, wd);
            wd = dup2(wa.z);
            fma2(acc[0][2], hA.x, wd); fma2(acc[1][2], hA.y, wd);
            fma2(acc[2][2], hB.x, wd); fma2(acc[3][2], hB.y, wd);
            wd = dup2(wa.w);
            fma2(acc[0][3], hA.x, wd); fma2(acc[1][3], hA.y, wd);
            fma2(acc[2][3], hB.x, wd); fma2(acc[3][3], hB.y, wd);
            wd = dup2(wb.x);
            fma2(acc[0][4], hA.x, wd); fma2(acc[1][4], hA.y, wd);
            fma2(acc[2][4], hB.x, wd); fma2(acc[3][4], hB.y, wd);
            wd = dup2(wb.y);
            fma2(acc[0][5], hA.x, wd); fma2(acc[1][5], hA.y, wd);
            fma2(acc[2][5], hB.x, wd); fma2(acc[3][5], hB.y, wd);
            wd = dup2(wb.z);
            fma2(acc[0][6], hA.x, wd); fma2(acc[1][6], hA.y, wd);
            fma2(acc[2][6], hB.x, wd); fma2(acc[3][6], hB.y, wd);
            wd = dup2(wb.w);
            fma2(acc[0][7], hA.x, wd); fma2(acc[1][7], hA.y, wd);
            fma2(acc[2][7], hB.x, wd); fma2(acc[3][7], hB.y, wd);
        }

        if (ct == 7) {
            float mx[8];
            #pragma unroll
            for (int j = 0; j < 8; j++) {
                float a0, b0, a1, b1, a2, b2, a3, b3;
                unpk2(acc[0][j], a0, b0); unpk2(acc[1][j], a1, b1);
                unpk2(acc[2][j], a2, b2); unpk2(acc[3][j], a3, b3);
                mx[j] = fmaxf(fmaxf(fmaxf(a0, b0), fmaxf(a1, b1)),
                              fmaxf(fmaxf(a2, b2), fmaxf(a3, b3)));
            }
            #pragma unroll
            for (int off = 1; off < 8; off <<= 1)
                #pragma unroll
                for (int j = 0; j < 8; j++)
                    mx[j] = fmaxf(mx[j], __shfl_xor_sync(0xffffffffu, mx[j], off));
            int k = kp*256 + w*32 + kl*8 + pl;
            atomicMaxF(&out[k], mx[pl] + __ldg(&b3g[k]));
        }
    }
}

// ---------------- J and Hinv (fp32 accumulation, double Gauss-Jordan) ----------------
__global__ void jh_kernel(const float* __restrict__ dt) {
    int b = blockIdx.x, tid = threadIdx.x;
    float dtv[6];
    #pragma unroll
    for (int j = 0; j < 6; j++) dtv[j] = __ldg(&dt[j]);
    float hacc[21];
    #pragma unroll
    for (int q = 0; q < 21; q++) hacc[q] = 0.f;
    for (int k = tid; k < KK; k += 256) {
        float f0k = d_f0[b*KK + k];
        float jv[6];
        #pragma unroll
        for (int j = 0; j < 6; j++) {
            jv[j] = (f0k - d_fj[((size_t)b*6 + j)*KK + k]) / dtv[j];
            d_J[((size_t)b*KK + k)*6 + j] = jv[j];
        }
        int q = 0;
        #pragma unroll
        for (int i = 0; i < 6; i++)
            #pragma unroll
            for (int j = i; j < 6; j++)
                hacc[q++] = fmaf(jv[i], jv[j], hacc[q]);
    }
    for (int off = 16; off; off >>= 1)
        #pragma unroll
        for (int q = 0; q < 21; q++) hacc[q] += __shfl_down_sync(0xffffffffu, hacc[q], off);
    __shared__ float shH[8][21];
    int lane = tid & 31, w = tid >> 5;
    if (lane == 0) { for (int q = 0; q < 21; q++) shH[w][q] = hacc[q]; }
    __syncthreads();
    if (tid == 0) {
        double s[21];
        for (int q = 0; q < 21; q++) { s[q] = 0.0; for (int w2 = 0; w2 < 8; w2++) s[q] += (double)shH[w2][q]; }
        double H[6][6];
        int q = 0;
        for (int i = 0; i < 6; i++)
            for (int j = i; j < 6; j++) { H[i][j] = s[q]; H[j][i] = s[q]; q++; }
        double M[6][12];
        for (int i = 0; i < 6; i++)
            for (int j = 0; j < 12; j++) M[i][j] = (j < 6) ? H[i][j] : ((j - 6 == i) ? 1.0 : 0.0);
        for (int col = 0; col < 6; col++) {
            int piv = col; double best = fabs(M[col][col]);
            for (int r2 = col + 1; r2 < 6; r2++)
                if (fabs(M[r2][col]) > best) { best = fabs(M[r2][col]); piv = r2; }
            if (piv != col)
                for (int j = 0; j < 12; j++) { double t = M[col][j]; M[col][j] = M[piv][j]; M[piv][j] = t; }
            double inv = 1.0 / M[col][col];
            for (int j = 0; j < 12; j++) M[col][j] *= inv;
            for (int r2 = 0; r2 < 6; r2++) {
                if (r2 == col) continue;
                double f = M[r2][col];
                for (int j = 0; j < 12; j++) M[r2][j] -= f * M[col][j];
            }
        }
        for (int i = 0; i < 6; i++)
            for (int j = 0; j < 6; j++) d_Hinv[b*36 + i*6 + j] = (float)M[i][6 + j];
    }
}

// ---------------- Gauss-Newton update (fp32 accumulation; resets f1) ----------------
__global__ void update_kernel() {
    int b = blockIdx.x, tid = threadIdx.x;
    float u[6] = {0,0,0,0,0,0};
    for (int k = tid; k < KK; k += 256) {
        float r = d_f1[b*KK + k] - d_f0[b*KK + k];
        d_r[b*KK + k] = r;
        d_f1[b*KK + k] = -INFINITY;
        #pragma unroll
        for (int j = 0; j < 6; j++) u[j] = fmaf(d_J[((size_t)b*KK + k)*6 + j], r, u[j]);
    }
    for (int off = 16; off; off >>= 1)
        #pragma unroll
        for (int j = 0; j < 6; j++) u[j] += __shfl_down_sync(0xffffffffu, u[j], off);
    __shared__ float shU[8][6];
    int lane = tid & 31, w = tid >> 5;
    if (lane == 0) { for (int j = 0; j < 6; j++) shU[w][j] = u[j]; }
    __syncthreads();
    if (tid == 0) {
        double uu[6];
        for (int j = 0; j < 6; j++) { uu[j] = 0.0; for (int w2 = 0; w2 < 8; w2++) uu[j] += (double)shU[w2][j]; }
        double dx[6];
        for (int i = 0; i < 6; i++) {
            double s2 = 0.0;
            for (int j = 0; j < 6; j++) s2 += (double)d_Hinv[b*36 + i*6 + j] * uu[j];
            dx[i] = -s2;
        }
        float E[12];
        double wv[3] = {dx[0], dx[1], dx[2]}, vv[3] = {dx[3], dx[4], dx[5]};
        se3_exp_d(wv, vv, E);
        float G[12];
        for (int i = 0; i < 12; i++) G[i] = d_gpose[b*12 + i];
        float Ng[12];
        for (int r2 = 0; r2 < 3; r2++) {
            for (int c = 0; c < 3; c++)
                Ng[r2*4 + c] = E[r2*4+0]*G[0*4+c] + E[r2*4+1]*G[1*4+c] + E[r2*4+2]*G[2*4+c];
            Ng[r2*4 + 3] = E[r2*4+0]*G[3] + E[r2*4+1]*G[7] + E[r2*4+2]*G[11] + E[r2*4+3];
        }
        for (int i = 0; i < 12; i++) d_gpose[b*12 + i] = Ng[i];
    }
}

// ---------------- est_g ----------------
__global__ void estg_kernel() {
    int tid = threadIdx.x;
    if (tid < 8) {
        int b = tid;
        const float* g = d_gpose + b*12;
        const float* m0 = d_mean0 + b*3;
        const float* m1 = d_mean1 + b*3;
        float e[12];
        for (int r = 0; r < 3; r++) {
            e[r*4+0] = g[r*4+0]; e[r*4+1] = g[r*4+1]; e[r*4+2] = g[r*4+2];
            e[r*4+3] = -(g[r*4+0]*m1[0] + g[r*4+1]*m1[1] + g[r*4+2]*m1[2]) + g[r*4+3] + m0[r];
        }
        for (int i = 0; i < 12; i++) d_estg[b*12 + i] = e[i];
    }
}

// ---------------- loss ----------------
__global__ void loss_kernel(const float* __restrict__ p_src) {
    int bi = blockIdx.x;
    int b = bi >> 3, seg = bi & 7;
    int tid = threadIdx.x;
    int n = seg*256 + tid;
    const float* p = p_src + ((size_t)b*NN + n)*3;
    float x = p[0], y = p[1], z = p[2];
    const float* e = d_estg + b*12;
    const float* q = d_igtinv + b*12;
    float s = 0.f;
    #pragma unroll
    for (int r = 0; r < 3; r++) {
        float ae = e[r*4+0]*x + e[r*4+1]*y + e[r*4+2]*z + e[r*4+3];
        float aq = q[r*4+0]*x + q[r*4+1]*y + q[r*4+2]*z + q[r*4+3];
        s += fabsf(ae - aq);
    }
    __shared__ float sr[256];
    sr[tid] = s;
    __syncthreads();
    for (int st = 128; st; st >>= 1) {
        if (tid < st) sr[tid] += sr[tid + st];
        __syncthreads();
    }
    if (tid == 0) d_lpart[bi] = sr[0];
}

// ---------------- output ----------------
__global__ void finish_kernel(float* __restrict__ out, int out_size) {
    int i = blockIdx.x*256 + threadIdx.x;
    if (i < BB*KK && i < out_size) out[i] = d_r[i];
    if (blockIdx.x == 0 && threadIdx.x == 0 && out_size > BB*KK) {
        double s = 0.0;
        for (int j = 0; j < 64; j++) s += (double)d_lpart[j];
        out[BB*KK] = (float)(s / (double)(BB*NN*3));
    }
}

// ---------------- host ----------------
extern "C" void kernel_launch(void* const* d_in, const int* in_sizes, int n_in,
                              void* d_out, int out_size) {
    const float* p_src = (const float*)d_in[0];
    const float* p_tgt = (const float*)d_in[1];
    const float* igt   = (const float*)d_in[2];
    const float* dt    = (const float*)d_in[3];
    const float* W1    = (const float*)d_in[4];
    const float* b1    = (const float*)d_in[5];
    const float* W2    = (const float*)d_in[6];
    const float* b2    = (const float*)d_in[7];
    const float* W3    = (const float*)d_in[8];
    const float* b3    = (const float*)d_in[9];
    float* out = (float*)d_out;

    cudaFuncSetAttribute(encode_kernel<0>, cudaFuncAttributeMaxDynamicSharedMemorySize, SMEM_BYTES);
    cudaFuncSetAttribute(encode_kernel<1>, cudaFuncAttributeMaxDynamicSharedMemorySize, SMEM_BYTES);

    prep_kernel<<<9, 256>>>(p_tgt, p_src, dt, igt);
    init_f_kernel<<<(BB*KK*2 + BB*6*KK + 255)/256, 256>>>();
    encode_kernel<0><<<dim3(NN/NP, BB*7), 256, SMEM_BYTES>>>(p_tgt, W1, b1, W2, b2, W3, b3);
    jh_kernel<<<BB, 256>>>(dt);
    for (int it = 0; it < 5; it++) {
        encode_kernel<1><<<dim3(NN/NP, BB), 256, SMEM_BYTES>>>(p_src, W1, b1, W2, b2, W3, b3);
        update_kernel<<<BB, 256>>>();
    }
    estg_kernel<<<1, 32>>>();
    loss_kernel<<<64, 256>>>(p_src);
    finish_kernel<<<(BB*KK + 256)/256 + 1, 256>>>(out, out_size);
}

// round 14
// speedup vs baseline: 1.4895x; 1.0246x over previous
#include <cuda_runtime.h>
#include <cuda_bf16.h>
#include <math.h>
#include <stdint.h>

#define BB 8
#define NN 2048
#define KK 1024
#define NP 64            // points per block

// ---------------- device state ----------------
__device__ float d_mean0[BB*3], d_mean1[BB*3];
__device__ float d_posesJ[7*12];
__device__ float d_gpose[BB*12];
__device__ float d_igtinv[BB*12];
__device__ float d_estg[BB*12];
__device__ float d_f0[BB*KK], d_fj[BB*6*KK], d_f1[BB*KK];
__device__ float d_J[BB*KK*6];
__device__ float d_Hinv[BB*36];
__device__ float d_r[BB*KK];
__device__ float d_lpart[64];
__device__ float d_hpart[BB*8*21];
__device__ float d_upart[BB*8*6];

typedef unsigned long long u64;

// ---------------- helpers ----------------
__device__ __forceinline__ void atomicMaxF(float* addr, float val) {
    if (val >= 0.f) atomicMax((int*)addr, __float_as_int(val));
    else            atomicMin((unsigned int*)addr, __float_as_uint(val));
}
__device__ __forceinline__ u64 dup2(float a) {
    u64 r; asm("mov.b64 %0,{%1,%1};" : "=l"(r) : "f"(a)); return r;
}
__device__ __forceinline__ u64 pk2(float a, float b) {
    u64 r; asm("mov.b64 %0,{%1,%2};" : "=l"(r) : "f"(a), "f"(b)); return r;
}
__device__ __forceinline__ void unpk2(u64 v, float& a, float& b) {
    asm("mov.b64 {%0,%1},%2;" : "=f"(a), "=f"(b) : "l"(v));
}
__device__ __forceinline__ void fma2(u64& d, u64 a, u64 b) {
    asm("fma.rn.f32x2 %0,%1,%2,%0;" : "+l"(d) : "l"(a), "l"(b));
}
__device__ __forceinline__ void cp16(uint32_t dst, const void* src) {
    asm volatile("cp.async.cg.shared.global [%0], [%1], 16;\n" :: "r"(dst), "l"(src));
}
#define CP_COMMIT() asm volatile("cp.async.commit_group;\n" ::: "memory")

// se3_exp (double internals), output 3x4 row-major float
__device__ void se3_exp_d(const double w[3], const double v[3], float out[12]) {
    double t2 = w[0]*w[0] + w[1]*w[1] + w[2]*w[2];
    double t = sqrt(t2);
    double A, Bc, Cc;
    if (t < 1e-6) {
        A  = 1.0 - t2/6.0;  Bc = 0.5 - t2/24.0;  Cc = 1.0/6.0 - t2/120.0;
    } else {
        double st = sin(t), ct = cos(t);
        A = st/t;  Bc = (1.0-ct)/t2;  Cc = (t-st)/(t2*t);
    }
    double W[3][3] = {{0.0,-w[2],w[1]},{w[2],0.0,-w[0]},{-w[1],w[0],0.0}};
    double W2m[3][3];
    for (int i = 0; i < 3; i++)
        for (int j = 0; j < 3; j++)
            W2m[i][j] = w[i]*w[j] - (i==j ? t2 : 0.0);
    double R[3][3], V[3][3];
    for (int i = 0; i < 3; i++)
        for (int j = 0; j < 3; j++) {
            double I = (i==j) ? 1.0 : 0.0;
            R[i][j] = I + A*W[i][j] + Bc*W2m[i][j];
            V[i][j] = I + Bc*W[i][j] + Cc*W2m[i][j];
        }
    for (int i = 0; i < 3; i++) {
        double p = V[i][0]*v[0] + V[i][1]*v[1] + V[i][2]*v[2];
        out[i*4+0] = (float)R[i][0]; out[i*4+1] = (float)R[i][1];
        out[i*4+2] = (float)R[i][2]; out[i*4+3] = (float)p;
    }
}

// ---------------- means (blocks 0..7) + setup (block 8) ----------------
__global__ void prep_kernel(const float* __restrict__ p_tgt, const float* __restrict__ p_src,
                            const float* __restrict__ dt, const float* __restrict__ igt_twist) {
    int tid = threadIdx.x;
    if (blockIdx.x < 8) {
        int b = blockIdx.x;
        float a[6] = {0,0,0,0,0,0};
        for (int n = tid; n < NN; n += 256) {
            const float* pt = p_tgt + ((size_t)b*NN + n)*3;
            const float* ps = p_src + ((size_t)b*NN + n)*3;
            a[0] += pt[0]; a[1] += pt[1]; a[2] += pt[2];
            a[3] += ps[0]; a[4] += ps[1]; a[5] += ps[2];
        }
        for (int off = 16; off; off >>= 1)
            #pragma unroll
            for (int q = 0; q < 6; q++) a[q] += __shfl_down_sync(0xffffffffu, a[q], off);
        __shared__ float sm[8][6];
        int lane = tid & 31, w = tid >> 5;
        if (lane == 0) { for (int q = 0; q < 6; q++) sm[w][q] = a[q]; }
        __syncthreads();
        if (tid < 6) {
            float s = 0.f;
            for (int w2 = 0; w2 < 8; w2++) s += sm[w2][tid];
            s *= (1.0f / NN);
            if (tid < 3) d_mean0[b*3 + tid] = s;
            else         d_mean1[b*3 + tid - 3] = s;
        }
    } else {
        if (tid < 7) {
            float out[12];
            if (tid == 0) {
                float I[12] = {1,0,0,0, 0,1,0,0, 0,0,1,0};
                for (int i = 0; i < 12; i++) out[i] = I[i];
            } else {
                int j = tid - 1;
                double w[3] = {0,0,0}, v[3] = {0,0,0};
                double val = -(double)__ldg(&dt[j]);
                if (j < 3) w[j] = val; else v[j-3] = val;
                se3_exp_d(w, v, out);
            }
            for (int i = 0; i < 12; i++) d_posesJ[tid*12 + i] = out[i];
        }
        if (tid >= 8 && tid < 16) {
            int b = tid - 8;
            float I[12] = {1,0,0,0, 0,1,0,0, 0,0,1,0};
            for (int i = 0; i < 12; i++) d_gpose[b*12 + i] = I[i];
        }
        if (tid >= 16 && tid < 24) {
            int b = tid - 16;
            double w[3], v[3];
            for (int i = 0; i < 3; i++) { w[i] = igt_twist[b*6 + i]; v[i] = igt_twist[b*6 + 3 + i]; }
            float g[12];
            se3_exp_d(w, v, g);
            float inv[12];
            for (int r = 0; r < 3; r++)
                for (int c = 0; c < 3; c++) inv[r*4 + c] = g[c*4 + r];
            for (int r = 0; r < 3; r++)
                inv[r*4 + 3] = -(g[0*4+r]*g[3] + g[1*4+r]*g[7] + g[2*4+r]*g[11]);
            for (int i = 0; i < 12; i++) d_igtinv[b*12 + i] = inv[i];
        }
    }
}

// init f0, fj, f1 to -INF (once; update maintains f1 afterwards)
__global__ void init_f_kernel() {
    int i = blockIdx.x*256 + threadIdx.x;
    if (i < BB*KK) d_f0[i] = -INFINITY;
    else if (i < BB*KK + BB*6*KK) d_fj[i - BB*KK] = -INFINITY;
    else if (i < BB*KK + BB*6*KK + BB*KK) d_f1[i - BB*KK - BB*6*KK] = -INFINITY;
}

// ---------------- fused encode (identical to R13 winner) ----------------
#define OFF_H2T  16384          /* 128 c x 64 = 8192 */
#define STRH2    64
#define SMEMF    24576
#define SMEM_BYTES (SMEMF*4)
#define OFF_PTS  0
#define OFF_SW1  192
#define OFF_SB1  384
#define OFF_SB2  448
#define OFF_H1   576
#define OFF_W2   8192

__device__ __forceinline__ void issue_tile(uint32_t sbase, int t,
                                           const float* __restrict__ W3g, int tid) {
    uint32_t buf = sbase + (uint32_t)(t & 3) * (4096u * 4u);
    int kp = t >> 3, ct = t & 7;
    const float* src = W3g + (size_t)(ct*16)*1024 + kp*256;
    #pragma unroll
    for (int i = 0; i < 4; i++) {
        int f4 = i*256 + tid;
        int row = f4 >> 6, col4 = f4 & 63;
        cp16(buf + (uint32_t)(row*256 + col4*4)*4u, src + (size_t)row*1024 + col4*4);
    }
}

template<int MODE>
__global__ __launch_bounds__(256, 2)
void encode_kernel(const float* __restrict__ P,
                   const float* __restrict__ W1g, const float* __restrict__ b1g,
                   const float* __restrict__ W2g, const float* __restrict__ b2g,
                   const float* __restrict__ W3g, const float* __restrict__ b3g) {
    extern __shared__ float sm[];
    int tid = threadIdx.x;
    uint32_t sbase = (uint32_t)__cvta_generic_to_shared(sm);

    int b; const float* pose; const float* mean; float* out;
    if (MODE == 0) {
        int bm = blockIdx.y;
        b = bm / 7; int m = bm % 7;
        pose = d_posesJ + m*12;
        mean = d_mean0 + b*3;
        out  = (m == 0) ? (d_f0 + b*KK) : (d_fj + ((size_t)b*6 + (m-1))*KK);
    } else {
        b = blockIdx.y;
        pose = d_gpose + b*12;
        mean = d_mean1 + b*3;
        out  = d_f1 + b*KK;
    }

    {
        const float4* w2v = (const float4*)W2g;
        #pragma unroll
        for (int i = 0; i < 8; i++)
            *(float4*)&sm[OFF_W2 + (tid + i*256)*4] = w2v[tid + i*256];
    }
    if (tid >= 64 && tid < 256) sm[OFF_SW1 + tid - 64] = W1g[tid - 64];
    if (tid < 64)  sm[OFF_SB1 + tid] = b1g[tid];
    if (tid >= 64 && tid < 192) sm[OFF_SB2 + tid - 64] = b2g[tid - 64];
    if (tid < NP) {
        int n = blockIdx.x * NP + tid;
        const float* pp = P + ((size_t)b*NN + n)*3;
        float dx = pp[0] - mean[0], dy = pp[1] - mean[1], dz = pp[2] - mean[2];
        sm[OFF_PTS + tid*3 + 0] = pose[0]*dx + pose[1]*dy + pose[2]*dz  + pose[3];
        sm[OFF_PTS + tid*3 + 1] = pose[4]*dx + pose[5]*dy + pose[6]*dz  + pose[7];
        sm[OFF_PTS + tid*3 + 2] = pose[8]*dx + pose[9]*dy + pose[10]*dz + pose[11];
    }
    __syncthreads();

    #pragma unroll
    for (int i = 0; i < 16; i++) {
        int idx = tid + i*256;
        int p = idx >> 6, c1 = idx & 63;
        float x = sm[OFF_PTS + p*3 + 0], y = sm[OFF_PTS + p*3 + 1], z = sm[OFF_PTS + p*3 + 2];
        float v = sm[OFF_SB1 + c1];
        v = fmaf(x, sm[OFF_SW1 + c1],       v);
        v = fmaf(y, sm[OFF_SW1 + 64 + c1],  v);
        v = fmaf(z, sm[OFF_SW1 + 128 + c1], v);
        sm[OFF_H1 + p*68 + c1] = fmaxf(v, 0.f);
    }
    __syncthreads();

    {
        int p = tid >> 2, r = tid & 3;
        u64 acc2[16];
        #pragma unroll
        for (int q = 0; q < 8; q++) {
            int c2 = r*4 + q*16;
            acc2[q*2+0] = pk2(sm[OFF_SB2 + c2],     sm[OFF_SB2 + c2 + 1]);
            acc2[q*2+1] = pk2(sm[OFF_SB2 + c2 + 2], sm[OFF_SB2 + c2 + 3]);
        }
        #pragma unroll
        for (int half = 0; half < 2; half++) {
            float hr[32];
            #pragma unroll
            for (int i = 0; i < 8; i++) {
                float4 h4 = *(const float4*)&sm[OFF_H1 + p*68 + half*32 + i*4];
                hr[i*4+0] = h4.x; hr[i*4+1] = h4.y; hr[i*4+2] = h4.z; hr[i*4+3] = h4.w;
            }
            #pragma unroll 8
            for (int c1i = 0; c1i < 32; c1i++) {
                int c1 = half*32 + c1i;
                u64 hd = dup2(hr[c1i]);
                #pragma unroll
                for (int q = 0; q < 8; q++) {
                    int c2 = r*4 + q*16;
                    ulonglong2 w2 = *(const ulonglong2*)&sm[OFF_W2 + c1*128 + c2];
                    fma2(acc2[q*2+0], hd, w2.x);
                    fma2(acc2[q*2+1], hd, w2.y);
                }
            }
        }
        #pragma unroll
        for (int q = 0; q < 8; q++) {
            int c2 = r*4 + q*16;
            float v0, v1, v2, v3;
            unpk2(acc2[q*2+0], v0, v1);
            unpk2(acc2[q*2+1], v2, v3);
            sm[OFF_H2T + (c2+0)*STRH2 + p] = fmaxf(v0, 0.f);
            sm[OFF_H2T + (c2+1)*STRH2 + p] = fmaxf(v1, 0.f);
            sm[OFF_H2T + (c2+2)*STRH2 + p] = fmaxf(v2, 0.f);
            sm[OFF_H2T + (c2+3)*STRH2 + p] = fmaxf(v3, 0.f);
        }
    }
    __syncthreads();

    issue_tile(sbase, 0, W3g, tid); CP_COMMIT();
    issue_tile(sbase, 1, W3g, tid); CP_COMMIT();
    issue_tile(sbase, 2, W3g, tid); CP_COMMIT();

    int lane = tid & 31, w = tid >> 5;
    int pl = lane & 7, kl = lane >> 3;
    const float* hbase = &sm[OFF_H2T + pl*4];
    u64 acc[4][8];

    for (int t = 0; t < 32; t++) {
        int kp = t >> 3, ct = t & 7;
        if (t < 30)       asm volatile("cp.async.wait_group 2;\n" ::: "memory");
        else if (t == 30) asm volatile("cp.async.wait_group 1;\n" ::: "memory");
        else              asm volatile("cp.async.wait_group 0;\n" ::: "memory");
        __syncthreads();

        if (t + 3 < 32) { issue_tile(sbase, t + 3, W3g, tid); CP_COMMIT(); }

        if (ct == 0) {
            #pragma unroll
            for (int i = 0; i < 4; i++)
                #pragma unroll
                for (int j = 0; j < 8; j++) acc[i][j] = 0ull;
        }

        const float* wbase = &sm[(t & 3)*4096] + w*32 + kl*8;
        const float* hrow = hbase + (ct*16)*STRH2;

        #pragma unroll 4
        for (int c = 0; c < 16; c++) {
            ulonglong2 hA = *(const ulonglong2*)&hrow[c*STRH2];
            ulonglong2 hB = *(const ulonglong2*)&hrow[c*STRH2 + 32];
            float4 wa = *(const float4*)&wbase[c*256];
            float4 wb = *(const float4*)&wbase[c*256 + 4];
            u64 wd;
            wd = dup2(wa.x);
            fma2(acc[0][0], hA.x, wd); fma2(acc[1][0], hA.y, wd);
            fma2(acc[2][0], hB.x, wd); fma2(acc[3][0], hB.y, wd);
            wd = dup2(wa.y);
            fma2(acc[0][1], hA.x, wd); fma2(acc[1][1], hA.y, wd);
            fma2(acc[2][1], hB.x, wd); fma2(acc[3][1], hB.y, wd);
            wd = dup2(wa.z);
            fma2(acc[0][2], hA.x, wd); fma2(acc[1][2], hA.y, wd);
            fma2(acc[2][2], hB.x, wd); fma2(acc[3][2], hB.y, wd);
            wd = dup2(wa.w);
            fma2(acc[0][3], hA.x, wd); fma2(acc[1][3], hA.y, wd);
            fma2(acc[2][3], hB.x, wd); fma2(acc[3][3], hB.y, wd);
            wd = dup2(wb.x);
            fma2(acc[0][4], hA.x, wd); fma2(acc[1][4], hA.y, wd);
            fma2(acc[2][4], hB.x, wd); fma2(acc[3][4], hB.y, wd);
            wd = dup2(wb.y);
            fma2(acc[0][5], hA.x, wd); fma2(acc[1][5], hA.y, wd);
            fma2(acc[2][5], hB.x, wd); fma2(acc[3][5], hB.y, wd);
            wd = dup2(wb.z);
            fma2(acc[0][6], hA.x, wd); fma2(acc[1][6], hA.y, wd);
            fma2(acc[2][6], hB.x, wd); fma2(acc[3][6], hB.y, wd);
            wd = dup2(wb.w);
            fma2(acc[0][7], hA.x, wd); fma2(acc[1][7], hA.y, wd);
            fma2(acc[2][7], hB.x, wd); fma2(acc[3][7], hB.y, wd);
        }

        if (ct == 7) {
            float mx[8];
            #pragma unroll
            for (int j = 0; j < 8; j++) {
                float a0, b0, a1, b1, a2, b2, a3, b3;
                unpk2(acc[0][j], a0, b0); unpk2(acc[1][j], a1, b1);
                unpk2(acc[2][j], a2, b2); unpk2(acc[3][j], a3, b3);
                mx[j] = fmaxf(fmaxf(fmaxf(a0, b0), fmaxf(a1, b1)),
                              fmaxf(fmaxf(a2, b2), fmaxf(a3, b3)));
            }
            #pragma unroll
            for (int off = 1; off < 8; off <<= 1)
                #pragma unroll
                for (int j = 0; j < 8; j++)
                    mx[j] = fmaxf(mx[j], __shfl_xor_sync(0xffffffffu, mx[j], off));
            int k = kp*256 + w*32 + kl*8 + pl;
            atomicMaxF(&out[k], mx[pl] + __ldg(&b3g[k]));
        }
    }
}

// ---------------- J + H partial sums (64 blocks: 8 b x 8 seg, 128 thr) ----------------
__global__ __launch_bounds__(128, 8)
void jh_part_kernel(const float* __restrict__ dt) {
    int blk = blockIdx.x;
    int b = blk >> 3, seg = blk & 7;
    int tid = threadIdx.x;
    int k = seg*128 + tid;
    float dtv[6];
    #pragma unroll
    for (int j = 0; j < 6; j++) dtv[j] = __ldg(&dt[j]);

    float f0k = d_f0[b*KK + k];
    float jv[6];
    #pragma unroll
    for (int j = 0; j < 6; j++) {
        jv[j] = (f0k - d_fj[((size_t)b*6 + j)*KK + k]) / dtv[j];
        d_J[((size_t)b*KK + k)*6 + j] = jv[j];
    }
    float hacc[21];
    int q = 0;
    #pragma unroll
    for (int i = 0; i < 6; i++)
        #pragma unroll
        for (int j = i; j < 6; j++)
            hacc[q++] = jv[i] * jv[j];
    for (int off = 16; off; off >>= 1)
        #pragma unroll
        for (int qq = 0; qq < 21; qq++) hacc[qq] += __shfl_down_sync(0xffffffffu, hacc[qq], off);
    __shared__ float sh[4][21];
    int lane = tid & 31, w = tid >> 5;
    if (lane == 0) { for (int qq = 0; qq < 21; qq++) sh[w][qq] = hacc[qq]; }
    __syncthreads();
    if (tid < 21) {
        float s = sh[0][tid] + sh[1][tid] + sh[2][tid] + sh[3][tid];
        d_hpart[blk*21 + tid] = s;
    }
}

// ---------------- H finalize + Gauss-Jordan (8 blocks, 32 thr) ----------------
__global__ void jh_fin_kernel() {
    int b = blockIdx.x, tid = threadIdx.x;
    __shared__ double s[21];
    if (tid < 21) {
        double acc = 0.0;
        for (int seg = 0; seg < 8; seg++) acc += (double)d_hpart[(b*8 + seg)*21 + tid];
        s[tid] = acc;
    }
    __syncthreads();
    if (tid == 0) {
        double H[6][6];
        int q = 0;
        for (int i = 0; i < 6; i++)
            for (int j = i; j < 6; j++) { H[i][j] = s[q]; H[j][i] = s[q]; q++; }
        double M[6][12];
        for (int i = 0; i < 6; i++)
            for (int j = 0; j < 12; j++) M[i][j] = (j < 6) ? H[i][j] : ((j - 6 == i) ? 1.0 : 0.0);
        for (int col = 0; col < 6; col++) {
            int piv = col; double best = fabs(M[col][col]);
            for (int r2 = col + 1; r2 < 6; r2++)
                if (fabs(M[r2][col]) > best) { best = fabs(M[r2][col]); piv = r2; }
            if (piv != col)
                for (int j = 0; j < 12; j++) { double t = M[col][j]; M[col][j] = M[piv][j]; M[piv][j] = t; }
            double inv = 1.0 / M[col][col];
            for (int j = 0; j < 12; j++) M[col][j] *= inv;
            for (int r2 = 0; r2 < 6; r2++) {
                if (r2 == col) continue;
                double f = M[r2][col];
                for (int j = 0; j < 12; j++) M[r2][j] -= f * M[col][j];
            }
        }
        for (int i = 0; i < 6; i++)
            for (int j = 0; j < 6; j++) d_Hinv[b*36 + i*6 + j] = (float)M[i][6 + j];
    }
}

// ---------------- update partial (64 blocks: 8 b x 8 seg, 128 thr) ----------------
__global__ __launch_bounds__(128, 8)
void update_part_kernel() {
    int blk = blockIdx.x;
    int b = blk >> 3, seg = blk & 7;
    int tid = threadIdx.x;
    int k = seg*128 + tid;
    float r = d_f1[b*KK + k] - d_f0[b*KK + k];
    d_r[b*KK + k] = r;
    d_f1[b*KK + k] = -INFINITY;
    float u[6];
    #pragma unroll
    for (int j = 0; j < 6; j++) u[j] = d_J[((size_t)b*KK + k)*6 + j] * r;
    for (int off = 16; off; off >>= 1)
        #pragma unroll
        for (int j = 0; j < 6; j++) u[j] += __shfl_down_sync(0xffffffffu, u[j], off);
    __shared__ float sh[4][6];
    int lane = tid & 31, w = tid >> 5;
    if (lane == 0) { for (int j = 0; j < 6; j++) sh[w][j] = u[j]; }
    __syncthreads();
    if (tid < 6)
        d_upart[blk*6 + tid] = sh[0][tid] + sh[1][tid] + sh[2][tid] + sh[3][tid];
}

// ---------------- update finalize (8 blocks, 32 thr) ----------------
__global__ void update_fin_kernel() {
    int b = blockIdx.x, tid = threadIdx.x;
    __shared__ double su[6];
    if (tid < 6) {
        double acc = 0.0;
        for (int seg = 0; seg < 8; seg++) acc += (double)d_upart[(b*8 + seg)*6 + tid];
        su[tid] = acc;
    }
    __syncthreads();
    if (tid == 0) {
        double dx[6];
        for (int i = 0; i < 6; i++) {
            double s2 = 0.0;
            for (int j = 0; j < 6; j++) s2 += (double)d_Hinv[b*36 + i*6 + j] * su[j];
            dx[i] = -s2;
        }
        float E[12];
        double wv[3] = {dx[0], dx[1], dx[2]}, vv[3] = {dx[3], dx[4], dx[5]};
        se3_exp_d(wv, vv, E);
        float G[12];
        for (int i = 0; i < 12; i++) G[i] = d_gpose[b*12 + i];
        float Ng[12];
        for (int r2 = 0; r2 < 3; r2++) {
            for (int c = 0; c < 3; c++)
                Ng[r2*4 + c] = E[r2*4+0]*G[0*4+c] + E[r2*4+1]*G[1*4+c] + E[r2*4+2]*G[2*4+c];
            Ng[r2*4 + 3] = E[r2*4+0]*G[3] + E[r2*4+1]*G[7] + E[r2*4+2]*G[11] + E[r2*4+3];
        }
        for (int i = 0; i < 12; i++) d_gpose[b*12 + i] = Ng[i];
    }
}

// ---------------- est_g ----------------
__global__ void estg_kernel() {
    int tid = threadIdx.x;
    if (tid < 8) {
        int b = tid;
        const float* g = d_gpose + b*12;
        const float* m0 = d_mean0 + b*3;
        const float* m1 = d_mean1 + b*3;
        float e[12];
        for (int r = 0; r < 3; r++) {
            e[r*4+0] = g[r*4+0]; e[r*4+1] = g[r*4+1]; e[r*4+2] = g[r*4+2];
            e[r*4+3] = -(g[r*4+0]*m1[0] + g[r*4+1]*m1[1] + g[r*4+2]*m1[2]) + g[r*4+3] + m0[r];
        }
        for (int i = 0; i < 12; i++) d_estg[b*12 + i] = e[i];
    }
}

// ---------------- loss ----------------
__global__ void loss_kernel(const float* __restrict__ p_src) {
    int bi = blockIdx.x;
    int b = bi >> 3, seg = bi & 7;
    int tid = threadIdx.x;
    int n = seg*256 + tid;
    const float* p = p_src + ((size_t)b*NN + n)*3;
    float x = p[0], y = p[1], z = p[2];
    const float* e = d_estg + b*12;
    const float* q = d_igtinv + b*12;
    float s = 0.f;
    #pragma unroll
    for (int r = 0; r < 3; r++) {
        float ae = e[r*4+0]*x + e[r*4+1]*y + e[r*4+2]*z + e[r*4+3];
        float aq = q[r*4+0]*x + q[r*4+1]*y + q[r*4+2]*z + q[r*4+3];
        s += fabsf(ae - aq);
    }
    __shared__ float sr[256];
    sr[tid] = s;
    __syncthreads();
    for (int st = 128; st; st >>= 1) {
        if (tid < st) sr[tid] += sr[tid + st];
        __syncthreads();
    }
    if (tid == 0) d_lpart[bi] = sr[0];
}

// ---------------- output ----------------
__global__ void finish_kernel(float* __restrict__ out, int out_size) {
    int i = blockIdx.x*256 + threadIdx.x;
    if (i < BB*KK && i < out_size) out[i] = d_r[i];
    if (blockIdx.x == 0 && threadIdx.x == 0 && out_size > BB*KK) {
        double s = 0.0;
        for (int j = 0; j < 64; j++) s += (double)d_lpart[j];
        out[BB*KK] = (float)(s / (double)(BB*NN*3));
    }
}

// ---------------- host ----------------
extern "C" void kernel_launch(void* const* d_in, const int* in_sizes, int n_in,
                              void* d_out, int out_size) {
    const float* p_src = (const float*)d_in[0];
    const float* p_tgt = (const float*)d_in[1];
    const float* igt   = (const float*)d_in[2];
    const float* dt    = (const float*)d_in[3];
    const float* W1    = (const float*)d_in[4];
    const float* b1    = (const float*)d_in[5];
    const float* W2    = (const float*)d_in[6];
    const float* b2    = (const float*)d_in[7];
    const float* W3    = (const float*)d_in[8];
    const float* b3    = (const float*)d_in[9];
    float* out = (float*)d_out;

    cudaFuncSetAttribute(encode_kernel<0>, cudaFuncAttributeMaxDynamicSharedMemorySize, SMEM_BYTES);
    cudaFuncSetAttribute(encode_kernel<1>, cudaFuncAttributeMaxDynamicSharedMemorySize, SMEM_BYTES);

    prep_kernel<<<9, 256>>>(p_tgt, p_src, dt, igt);
    init_f_kernel<<<(BB*KK*2 + BB*6*KK + 255)/256, 256>>>();
    encode_kernel<0><<<dim3(NN/NP, BB*7), 256, SMEM_BYTES>>>(p_tgt, W1, b1, W2, b2, W3, b3);
    jh_part_kernel<<<64, 128>>>(dt);
    jh_fin_kernel<<<8, 32>>>();
    for (int it = 0; it < 5; it++) {
        encode_kernel<1><<<dim3(NN/NP, BB), 256, SMEM_BYTES>>>(p_src, W1, b1, W2, b2, W3, b3);
        update_part_kernel<<<64, 128>>>();
        update_fin_kernel<<<8, 32>>>();
    }
    estg_kernel<<<1, 32>>>();
    loss_kernel<<<64, 256>>>(p_src);
    finish_kernel<<<(BB*KK + 256)/256 + 1, 256>>>(out, out_size);
}

// round 15
// speedup vs baseline: 1.5301x; 1.0273x over previous
#include <cuda_runtime.h>
#include <cuda_bf16.h>
#include <math.h>
#include <stdint.h>

#define BB 8
#define NN 2048
#define KK 1024
#define NP 64            // points per block

// ---------------- device state ----------------
__device__ float d_mean0[BB*3], d_mean1[BB*3];
__device__ float d_posesJ[7*12];
__device__ float d_gpose[BB*12];
__device__ float d_igtinv[BB*12];
__device__ float d_estg[BB*12];
__device__ float d_f0[BB*KK], d_fj[BB*6*KK], d_f1[BB*KK];
__device__ float d_J[BB*KK*6];
__device__ float d_Hinv[BB*36];
__device__ float d_r[BB*KK];
__device__ float d_lpart[64];
__device__ float d_hpart[BB*8*21];
__device__ float d_upart[BB*8*6];

typedef unsigned long long u64;

// ---------------- helpers ----------------
__device__ __forceinline__ void atomicMaxF(float* addr, float val) {
    if (val >= 0.f) atomicMax((int*)addr, __float_as_int(val));
    else            atomicMin((unsigned int*)addr, __float_as_uint(val));
}
__device__ __forceinline__ u64 dup2(float a) {
    u64 r; asm("mov.b64 %0,{%1,%1};" : "=l"(r) : "f"(a)); return r;
}
__device__ __forceinline__ u64 pk2(float a, float b) {
    u64 r; asm("mov.b64 %0,{%1,%2};" : "=l"(r) : "f"(a), "f"(b)); return r;
}
__device__ __forceinline__ void unpk2(u64 v, float& a, float& b) {
    asm("mov.b64 {%0,%1},%2;" : "=f"(a), "=f"(b) : "l"(v));
}
__device__ __forceinline__ void fma2(u64& d, u64 a, u64 b) {
    asm("fma.rn.f32x2 %0,%1,%2,%0;" : "+l"(d) : "l"(a), "l"(b));
}
__device__ __forceinline__ void cp16(uint32_t dst, const void* src) {
    asm volatile("cp.async.cg.shared.global [%0], [%1], 16;\n" :: "r"(dst), "l"(src));
}
#define CP_COMMIT() asm volatile("cp.async.commit_group;\n" ::: "memory")

// se3_exp (double internals), output 3x4 row-major float
__device__ void se3_exp_d(const double w[3], const double v[3], float out[12]) {
    double t2 = w[0]*w[0] + w[1]*w[1] + w[2]*w[2];
    double t = sqrt(t2);
    double A, Bc, Cc;
    if (t < 1e-6) {
        A  = 1.0 - t2/6.0;  Bc = 0.5 - t2/24.0;  Cc = 1.0/6.0 - t2/120.0;
    } else {
        double st = sin(t), ct = cos(t);
        A = st/t;  Bc = (1.0-ct)/t2;  Cc = (t-st)/(t2*t);
    }
    double W[3][3] = {{0.0,-w[2],w[1]},{w[2],0.0,-w[0]},{-w[1],w[0],0.0}};
    double W2m[3][3];
    for (int i = 0; i < 3; i++)
        for (int j = 0; j < 3; j++)
            W2m[i][j] = w[i]*w[j] - (i==j ? t2 : 0.0);
    double R[3][3], V[3][3];
    for (int i = 0; i < 3; i++)
        for (int j = 0; j < 3; j++) {
            double I = (i==j) ? 1.0 : 0.0;
            R[i][j] = I + A*W[i][j] + Bc*W2m[i][j];
            V[i][j] = I + Bc*W[i][j] + Cc*W2m[i][j];
        }
    for (int i = 0; i < 3; i++) {
        double p = V[i][0]*v[0] + V[i][1]*v[1] + V[i][2]*v[2];
        out[i*4+0] = (float)R[i][0]; out[i*4+1] = (float)R[i][1];
        out[i*4+2] = (float)R[i][2]; out[i*4+3] = (float)p;
    }
}

// ---------------- means (blocks 0..7) + setup (block 8) ----------------
__global__ void prep_kernel(const float* __restrict__ p_tgt, const float* __restrict__ p_src,
                            const float* __restrict__ dt, const float* __restrict__ igt_twist) {
    int tid = threadIdx.x;
    if (blockIdx.x < 8) {
        int b = blockIdx.x;
        float a[6] = {0,0,0,0,0,0};
        for (int n = tid; n < NN; n += 256) {
            const float* pt = p_tgt + ((size_t)b*NN + n)*3;
            const float* ps = p_src + ((size_t)b*NN + n)*3;
            a[0] += pt[0]; a[1] += pt[1]; a[2] += pt[2];
            a[3] += ps[0]; a[4] += ps[1]; a[5] += ps[2];
        }
        for (int off = 16; off; off >>= 1)
            #pragma unroll
            for (int q = 0; q < 6; q++) a[q] += __shfl_down_sync(0xffffffffu, a[q], off);
        __shared__ float sm[8][6];
        int lane = tid & 31, w = tid >> 5;
        if (lane == 0) { for (int q = 0; q < 6; q++) sm[w][q] = a[q]; }
        __syncthreads();
        if (tid < 6) {
            float s = 0.f;
            for (int w2 = 0; w2 < 8; w2++) s += sm[w2][tid];
            s *= (1.0f / NN);
            if (tid < 3) d_mean0[b*3 + tid] = s;
            else         d_mean1[b*3 + tid - 3] = s;
        }
    } else {
        if (tid < 7) {
            float out[12];
            if (tid == 0) {
                float I[12] = {1,0,0,0, 0,1,0,0, 0,0,1,0};
                for (int i = 0; i < 12; i++) out[i] = I[i];
            } else {
                int j = tid - 1;
                double w[3] = {0,0,0}, v[3] = {0,0,0};
                double val = -(double)__ldg(&dt[j]);
                if (j < 3) w[j] = val; else v[j-3] = val;
                se3_exp_d(w, v, out);
            }
            for (int i = 0; i < 12; i++) d_posesJ[tid*12 + i] = out[i];
        }
        if (tid >= 8 && tid < 16) {
            int b = tid - 8;
            float I[12] = {1,0,0,0, 0,1,0,0, 0,0,1,0};
            for (int i = 0; i < 12; i++) d_gpose[b*12 + i] = I[i];
        }
        if (tid >= 16 && tid < 24) {
            int b = tid - 16;
            double w[3], v[3];
            for (int i = 0; i < 3; i++) { w[i] = igt_twist[b*6 + i]; v[i] = igt_twist[b*6 + 3 + i]; }
            float g[12];
            se3_exp_d(w, v, g);
            float inv[12];
            for (int r = 0; r < 3; r++)
                for (int c = 0; c < 3; c++) inv[r*4 + c] = g[c*4 + r];
            for (int r = 0; r < 3; r++)
                inv[r*4 + 3] = -(g[0*4+r]*g[3] + g[1*4+r]*g[7] + g[2*4+r]*g[11]);
            for (int i = 0; i < 12; i++) d_igtinv[b*12 + i] = inv[i];
        }
    }
}

// init f0, fj, f1 to -INF (once; update maintains f1 afterwards)
__global__ void init_f_kernel() {
    int i = blockIdx.x*256 + threadIdx.x;
    if (i < BB*KK) d_f0[i] = -INFINITY;
    else if (i < BB*KK + BB*6*KK) d_fj[i - BB*KK] = -INFINITY;
    else if (i < BB*KK + BB*6*KK + BB*KK) d_f1[i - BB*KK - BB*6*KK] = -INFINITY;
}

// ---------------- fused encode ----------------
// 256 threads, 64 points. Phase B: 32 tiles (4 k-passes x 8 c-tiles of 16 c).
// W3 ring is PER-WARP (warp w only reads k-cols w*32..+31): warp w owns a
// 4-deep ring of 16c x 32k tiles (512 floats each) at sm[w*2048 ..]. Staging
// is warp-local cp.async; sync = cp.async.wait_group + __syncwarp only.
// ZERO __syncthreads in the phase-B loop.
#define OFF_H2T  16384          /* 128 c x 64 = 8192 */
#define STRH2    64
#define SMEMF    24576
#define SMEM_BYTES (SMEMF*4)
// A-phase aliases inside ring region [0,16384):
#define OFF_PTS  0
#define OFF_SW1  192
#define OFF_SB1  384
#define OFF_SB2  448
#define OFF_H1   576            /* 64 x 68 -> ends 4928 < 8192 */
#define OFF_W2   8192

// Warp-local stage of tile t (t = kp*8 + ct): rows c = ct*16..+15, cols w*32..+31.
__device__ __forceinline__ void issue_tile_w(uint32_t sbase, int t,
                                             const float* __restrict__ W3g,
                                             int w, int lane) {
    uint32_t buf = sbase + (uint32_t)(w*2048 + (t & 3)*512) * 4u;
    int kp = t >> 3, ct = t & 7;
    const float* src = W3g + (size_t)(ct*16)*1024 + kp*256 + w*32;
    #pragma unroll
    for (int i = 0; i < 4; i++) {
        int f4 = i*32 + lane;              // 128 float4 = 16 rows x 8
        int row = f4 >> 3, col4 = f4 & 7;
        cp16(buf + (uint32_t)(row*32 + col4*4)*4u, src + (size_t)row*1024 + col4*4);
    }
}

template<int MODE>
__global__ __launch_bounds__(256, 2)
void encode_kernel(const float* __restrict__ P,
                   const float* __restrict__ W1g, const float* __restrict__ b1g,
                   const float* __restrict__ W2g, const float* __restrict__ b2g,
                   const float* __restrict__ W3g, const float* __restrict__ b3g) {
    extern __shared__ float sm[];
    int tid = threadIdx.x;
    uint32_t sbase = (uint32_t)__cvta_generic_to_shared(sm);

    int b; const float* pose; const float* mean; float* out;
    if (MODE == 0) {
        int bm = blockIdx.y;
        b = bm / 7; int m = bm % 7;
        pose = d_posesJ + m*12;
        mean = d_mean0 + b*3;
        out  = (m == 0) ? (d_f0 + b*KK) : (d_fj + ((size_t)b*6 + (m-1))*KK);
    } else {
        b = blockIdx.y;
        pose = d_gpose + b*12;
        mean = d_mean1 + b*3;
        out  = d_f1 + b*KK;
    }

    // phase A0: stage weights + transform points
    {
        const float4* w2v = (const float4*)W2g;
        #pragma unroll
        for (int i = 0; i < 8; i++)
            *(float4*)&sm[OFF_W2 + (tid + i*256)*4] = w2v[tid + i*256];
    }
    if (tid >= 64 && tid < 256) sm[OFF_SW1 + tid - 64] = W1g[tid - 64];
    if (tid < 64)  sm[OFF_SB1 + tid] = b1g[tid];
    if (tid >= 64 && tid < 192) sm[OFF_SB2 + tid - 64] = b2g[tid - 64];
    if (tid < NP) {
        int n = blockIdx.x * NP + tid;
        const float* pp = P + ((size_t)b*NN + n)*3;
        float dx = pp[0] - mean[0], dy = pp[1] - mean[1], dz = pp[2] - mean[2];
        sm[OFF_PTS + tid*3 + 0] = pose[0]*dx + pose[1]*dy + pose[2]*dz  + pose[3];
        sm[OFF_PTS + tid*3 + 1] = pose[4]*dx + pose[5]*dy + pose[6]*dz  + pose[7];
        sm[OFF_PTS + tid*3 + 2] = pose[8]*dx + pose[9]*dy + pose[10]*dz + pose[11];
    }
    __syncthreads();

    // phase A1: h1 = relu(pt @ W1 + b1), 64 x 64 (stride 68)
    #pragma unroll
    for (int i = 0; i < 16; i++) {
        int idx = tid + i*256;
        int p = idx >> 6, c1 = idx & 63;
        float x = sm[OFF_PTS + p*3 + 0], y = sm[OFF_PTS + p*3 + 1], z = sm[OFF_PTS + p*3 + 2];
        float v = sm[OFF_SB1 + c1];
        v = fmaf(x, sm[OFF_SW1 + c1],       v);
        v = fmaf(y, sm[OFF_SW1 + 64 + c1],  v);
        v = fmaf(z, sm[OFF_SW1 + 128 + c1], v);
        sm[OFF_H1 + p*68 + c1] = fmaxf(v, 0.f);
    }
    __syncthreads();

    // phase A2: h2T[c2][p] = relu(h1[p] @ W2[:,c2] + b2), f32x2 accumulation
    {
        int p = tid >> 2, r = tid & 3;
        u64 acc2[16];
        #pragma unroll
        for (int q = 0; q < 8; q++) {
            int c2 = r*4 + q*16;
            acc2[q*2+0] = pk2(sm[OFF_SB2 + c2],     sm[OFF_SB2 + c2 + 1]);
            acc2[q*2+1] = pk2(sm[OFF_SB2 + c2 + 2], sm[OFF_SB2 + c2 + 3]);
        }
        #pragma unroll
        for (int half = 0; half < 2; half++) {
            float hr[32];
            #pragma unroll
            for (int i = 0; i < 8; i++) {
                float4 h4 = *(const float4*)&sm[OFF_H1 + p*68 + half*32 + i*4];
                hr[i*4+0] = h4.x; hr[i*4+1] = h4.y; hr[i*4+2] = h4.z; hr[i*4+3] = h4.w;
            }
            #pragma unroll 8
            for (int c1i = 0; c1i < 32; c1i++) {
                int c1 = half*32 + c1i;
                u64 hd = dup2(hr[c1i]);
                #pragma unroll
                for (int q = 0; q < 8; q++) {
                    int c2 = r*4 + q*16;
                    ulonglong2 w2 = *(const ulonglong2*)&sm[OFF_W2 + c1*128 + c2];
                    fma2(acc2[q*2+0], hd, w2.x);
                    fma2(acc2[q*2+1], hd, w2.y);
                }
            }
        }
        #pragma unroll
        for (int q = 0; q < 8; q++) {
            int c2 = r*4 + q*16;
            float v0, v1, v2, v3;
            unpk2(acc2[q*2+0], v0, v1);
            unpk2(acc2[q*2+1], v2, v3);
            sm[OFF_H2T + (c2+0)*STRH2 + p] = fmaxf(v0, 0.f);
            sm[OFF_H2T + (c2+1)*STRH2 + p] = fmaxf(v1, 0.f);
            sm[OFF_H2T + (c2+2)*STRH2 + p] = fmaxf(v2, 0.f);
            sm[OFF_H2T + (c2+3)*STRH2 + p] = fmaxf(v3, 0.f);
        }
    }
    __syncthreads();   // H2T ready; ring region free. LAST block-wide barrier.

    // phase B: barrier-free, warp-private W3 ring
    int lane = tid & 31, w = tid >> 5;
    int pl = lane & 7, kl = lane >> 3;
    const float* hbase = &sm[OFF_H2T + pl*4];
    const float* ring = &sm[w*2048];
    u64 acc[4][8];

    issue_tile_w(sbase, 0, W3g, w, lane); CP_COMMIT();
    issue_tile_w(sbase, 1, W3g, w, lane); CP_COMMIT();
    issue_tile_w(sbase, 2, W3g, w, lane); CP_COMMIT();

    for (int t = 0; t < 32; t++) {
        int kp = t >> 3, ct = t & 7;
        if (t < 30)       asm volatile("cp.async.wait_group 2;\n" ::: "memory");
        else if (t == 30) asm volatile("cp.async.wait_group 1;\n" ::: "memory");
        else              asm volatile("cp.async.wait_group 0;\n" ::: "memory");
        __syncwarp();     // tile t visible to all lanes of this warp

        if (t + 3 < 32) { issue_tile_w(sbase, t + 3, W3g, w, lane); CP_COMMIT(); }

        if (ct == 0) {
            #pragma unroll
            for (int i = 0; i < 4; i++)
                #pragma unroll
                for (int j = 0; j < 8; j++) acc[i][j] = 0ull;
        }

        const float* wbase = ring + (t & 3)*512 + kl*8;
        const float* hrow = hbase + (ct*16)*STRH2;

        #pragma unroll 4
        for (int c = 0; c < 16; c++) {
            ulonglong2 hA = *(const ulonglong2*)&hrow[c*STRH2];
            ulonglong2 hB = *(const ulonglong2*)&hrow[c*STRH2 + 32];
            float4 wa = *(const float4*)&wbase[c*32];
            float4 wb = *(const float4*)&wbase[c*32 + 4];
            u64 wd;
            wd = dup2(wa.x);
            fma2(acc[0][0], hA.x, wd); fma2(acc[1][0], hA.y, wd);
            fma2(acc[2][0], hB.x, wd); fma2(acc[3][0], hB.y, wd);
            wd = dup2(wa.y);
            fma2(acc[0][1], hA.x, wd); fma2(acc[1][1], hA.y, wd);
            fma2(acc[2][1], hB.x, wd); fma2(acc[3][1], hB.y, wd);
            wd = dup2(wa.z);
            fma2(acc[0][2], hA.x, wd); fma2(acc[1][2], hA.y, wd);
            fma2(acc[2][2], hB.x, wd); fma2(acc[3][2], hB.y, wd);
            wd = dup2(wa.w);
            fma2(acc[0][3], hA.x, wd); fma2(acc[1][3], hA.y, wd);
            fma2(acc[2][3], hB.x, wd); fma2(acc[3][3], hB.y, wd);
            wd = dup2(wb.x);
            fma2(acc[0][4], hA.x, wd); fma2(acc[1][4], hA.y, wd);
            fma2(acc[2][4], hB.x, wd); fma2(acc[3][4], hB.y, wd);
            wd = dup2(wb.y);
            fma2(acc[0][5], hA.x, wd); fma2(acc[1][5], hA.y, wd);
            fma2(acc[2][5], hB.x, wd); fma2(acc[3][5], hB.y, wd);
            wd = dup2(wb.z);
            fma2(acc[0][6], hA.x, wd); fma2(acc[1][6], hA.y, wd);
            fma2(acc[2][6], hB.x, wd); fma2(acc[3][6], hB.y, wd);
            wd = dup2(wb.w);
            fma2(acc[0][7], hA.x, wd); fma2(acc[1][7], hA.y, wd);
            fma2(acc[2][7], hB.x, wd); fma2(acc[3][7], hB.y, wd);
        }

        if (ct == 7) {
            float mx[8];
            #pragma unroll
            for (int j = 0; j < 8; j++) {
                float a0, b0, a1, b1, a2, b2, a3, b3;
                unpk2(acc[0][j], a0, b0); unpk2(acc[1][j], a1, b1);
                unpk2(acc[2][j], a2, b2); unpk2(acc[3][j], a3, b3);
                mx[j] = fmaxf(fmaxf(fmaxf(a0, b0), fmaxf(a1, b1)),
                              fmaxf(fmaxf(a2, b2), fmaxf(a3, b3)));
            }
            #pragma unroll
            for (int off = 1; off < 8; off <<= 1)
                #pragma unroll
                for (int j = 0; j < 8; j++)
                    mx[j] = fmaxf(mx[j], __shfl_xor_sync(0xffffffffu, mx[j], off));
            int k = kp*256 + w*32 + kl*8 + pl;
            atomicMaxF(&out[k], mx[pl] + __ldg(&b3g[k]));
        }
    }
}

// ---------------- J + H partial sums (64 blocks: 8 b x 8 seg, 128 thr) ----------------
__global__ __launch_bounds__(128, 8)
void jh_part_kernel(const float* __restrict__ dt) {
    int blk = blockIdx.x;
    int b = blk >> 3, seg = blk & 7;
    int tid = threadIdx.x;
    int k = seg*128 + tid;
    float dtv[6];
    #pragma unroll
    for (int j = 0; j < 6; j++) dtv[j] = __ldg(&dt[j]);

    float f0k = d_f0[b*KK + k];
    float jv[6];
    #pragma unroll
    for (int j = 0; j < 6; j++) {
        jv[j] = (f0k - d_fj[((size_t)b*6 + j)*KK + k]) / dtv[j];
        d_J[((size_t)b*KK + k)*6 + j] = jv[j];
    }
    float hacc[21];
    int q = 0;
    #pragma unroll
    for (int i = 0; i < 6; i++)
        #pragma unroll
        for (int j = i; j < 6; j++)
            hacc[q++] = jv[i] * jv[j];
    for (int off = 16; off; off >>= 1)
        #pragma unroll
        for (int qq = 0; qq < 21; qq++) hacc[qq] += __shfl_down_sync(0xffffffffu, hacc[qq], off);
    __shared__ float sh[4][21];
    int lane = tid & 31, w = tid >> 5;
    if (lane == 0) { for (int qq = 0; qq < 21; qq++) sh[w][qq] = hacc[qq]; }
    __syncthreads();
    if (tid < 21) {
        float s = sh[0][tid] + sh[1][tid] + sh[2][tid] + sh[3][tid];
        d_hpart[blk*21 + tid] = s;
    }
}

// ---------------- H finalize + Gauss-Jordan (8 blocks, 32 thr) ----------------
__global__ void jh_fin_kernel() {
    int b = blockIdx.x, tid = threadIdx.x;
    __shared__ double s[21];
    if (tid < 21) {
        double acc = 0.0;
        for (int seg = 0; seg < 8; seg++) acc += (double)d_hpart[(b*8 + seg)*21 + tid];
        s[tid] = acc;
    }
    __syncthreads();
    if (tid == 0) {
        double H[6][6];
        int q = 0;
        for (int i = 0; i < 6; i++)
            for (int j = i; j < 6; j++) { H[i][j] = s[q]; H[j][i] = s[q]; q++; }
        double M[6][12];
        for (int i = 0; i < 6; i++)
            for (int j = 0; j < 12; j++) M[i][j] = (j < 6) ? H[i][j] : ((j - 6 == i) ? 1.0 : 0.0);
        for (int col = 0; col < 6; col++) {
            int piv = col; double best = fabs(M[col][col]);
            for (int r2 = col + 1; r2 < 6; r2++)
                if (fabs(M[r2][col]) > best) { best = fabs(M[r2][col]); piv = r2; }
            if (piv != col)
                for (int j = 0; j < 12; j++) { double t = M[col][j]; M[col][j] = M[piv][j]; M[piv][j] = t; }
            double inv = 1.0 / M[col][col];
            for (int j = 0; j < 12; j++) M[col][j] *= inv;
            for (int r2 = 0; r2 < 6; r2++) {
                if (r2 == col) continue;
                double f = M[r2][col];
                for (int j = 0; j < 12; j++) M[r2][j] -= f * M[col][j];
            }
        }
        for (int i = 0; i < 6; i++)
            for (int j = 0; j < 6; j++) d_Hinv[b*36 + i*6 + j] = (float)M[i][6 + j];
    }
}

// ---------------- update partial (64 blocks: 8 b x 8 seg, 128 thr) ----------------
__global__ __launch_bounds__(128, 8)
void update_part_kernel() {
    int blk = blockIdx.x;
    int b = blk >> 3, seg = blk & 7;
    int tid = threadIdx.x;
    int k = seg*128 + tid;
    float r = d_f1[b*KK + k] - d_f0[b*KK + k];
    d_r[b*KK + k] = r;
    d_f1[b*KK + k] = -INFINITY;
    float u[6];
    #pragma unroll
    for (int j = 0; j < 6; j++) u[j] = d_J[((size_t)b*KK + k)*6 + j] * r;
    for (int off = 16; off; off >>= 1)
        #pragma unroll
        for (int j = 0; j < 6; j++) u[j] += __shfl_down_sync(0xffffffffu, u[j], off);
    __shared__ float sh[4][6];
    int lane = tid & 31, w = tid >> 5;
    if (lane == 0) { for (int j = 0; j < 6; j++) sh[w][j] = u[j]; }
    __syncthreads();
    if (tid < 6)
        d_upart[blk*6 + tid] = sh[0][tid] + sh[1][tid] + sh[2][tid] + sh[3][tid];
}

// ---------------- update finalize (8 blocks, 32 thr) ----------------
__global__ void update_fin_kernel() {
    int b = blockIdx.x, tid = threadIdx.x;
    __shared__ double su[6];
    if (tid < 6) {
        double acc = 0.0;
        for (int seg = 0; seg < 8; seg++) acc += (double)d_upart[(b*8 + seg)*6 + tid];
        su[tid] = acc;
    }
    __syncthreads();
    if (tid == 0) {
        double dx[6];
        for (int i = 0; i < 6; i++) {
            double s2 = 0.0;
            for (int j = 0; j < 6; j++) s2 += (double)d_Hinv[b*36 + i*6 + j] * su[j];
            dx[i] = -s2;
        }
        float E[12];
        double wv[3] = {dx[0], dx[1], dx[2]}, vv[3] = {dx[3], dx[4], dx[5]};
        se3_exp_d(wv, vv, E);
        float G[12];
        for (int i = 0; i < 12; i++) G[i] = d_gpose[b*12 + i];
        float Ng[12];
        for (int r2 = 0; r2 < 3; r2++) {
            for (int c = 0; c < 3; c++)
                Ng[r2*4 + c] = E[r2*4+0]*G[0*4+c] + E[r2*4+1]*G[1*4+c] + E[r2*4+2]*G[2*4+c];
            Ng[r2*4 + 3] = E[r2*4+0]*G[3] + E[r2*4+1]*G[7] + E[r2*4+2]*G[11] + E[r2*4+3];
        }
        for (int i = 0; i < 12; i++) d_gpose[b*12 + i] = Ng[i];
    }
}

// ---------------- est_g ----------------
__global__ void estg_kernel() {
    int tid = threadIdx.x;
    if (tid < 8) {
        int b = tid;
        const float* g = d_gpose + b*12;
        const float* m0 = d_mean0 + b*3;
        const float* m1 = d_mean1 + b*3;
        float e[12];
        for (int r = 0; r < 3; r++) {
            e[r*4+0] = g[r*4+0]; e[r*4+1] = g[r*4+1]; e[r*4+2] = g[r*4+2];
            e[r*4+3] = -(g[r*4+0]*m1[0] + g[r*4+1]*m1[1] + g[r*4+2]*m1[2]) + g[r*4+3] + m0[r];
        }
        for (int i = 0; i < 12; i++) d_estg[b*12 + i] = e[i];
    }
}

// ---------------- loss ----------------
__global__ void loss_kernel(const float* __restrict__ p_src) {
    int bi = blockIdx.x;
    int b = bi >> 3, seg = bi & 7;
    int tid = threadIdx.x;
    int n = seg*256 + tid;
    const float* p = p_src + ((size_t)b*NN + n)*3;
    float x = p[0], y = p[1], z = p[2];
    const float* e = d_estg + b*12;
    const float* q = d_igtinv + b*12;
    float s = 0.f;
    #pragma unroll
    for (int r = 0; r < 3; r++) {
        float ae = e[r*4+0]*x + e[r*4+1]*y + e[r*4+2]*z + e[r*4+3];
        float aq = q[r*4+0]*x + q[r*4+1]*y + q[r*4+2]*z + q[r*4+3];
        s += fabsf(ae - aq);
    }
    __shared__ float sr[256];
    sr[tid] = s;
    __syncthreads();
    for (int st = 128; st; st >>= 1) {
        if (tid < st) sr[tid] += sr[tid + st];
        __syncthreads();
    }
    if (tid == 0) d_lpart[bi] = sr[0];
}

// ---------------- output ----------------
__global__ void finish_kernel(float* __restrict__ out, int out_size) {
    int i = blockIdx.x*256 + threadIdx.x;
    if (i < BB*KK && i < out_size) out[i] = d_r[i];
    if (blockIdx.x == 0 && threadIdx.x == 0 && out_size > BB*KK) {
        double s = 0.0;
        for (int j = 0; j < 64; j++) s += (double)d_lpart[j];
        out[BB*KK] = (float)(s / (double)(BB*NN*3));
    }
}

// ---------------- host ----------------
extern "C" void kernel_launch(void* const* d_in, const int* in_sizes, int n_in,
                              void* d_out, int out_size) {
    const float* p_src = (const float*)d_in[0];
    const float* p_tgt = (const float*)d_in[1];
    const float* igt   = (const float*)d_in[2];
    const float* dt    = (const float*)d_in[3];
    const float* W1    = (const float*)d_in[4];
    const float* b1    = (const float*)d_in[5];
    const float* W2    = (const float*)d_in[6];
    const float* b2    = (const float*)d_in[7];
    const float* W3    = (const float*)d_in[8];
    const float* b3    = (const float*)d_in[9];
    float* out = (float*)d_out;

    cudaFuncSetAttribute(encode_kernel<0>, cudaFuncAttributeMaxDynamicSharedMemorySize, SMEM_BYTES);
    cudaFuncSetAttribute(encode_kernel<1>, cudaFuncAttributeMaxDynamicSharedMemorySize, SMEM_BYTES);

    prep_kernel<<<9, 256>>>(p_tgt, p_src, dt, igt);
    init_f_kernel<<<(BB*KK*2 + BB*6*KK + 255)/256, 256>>>();
    encode_kernel<0><<<dim3(NN/NP, BB*7), 256, SMEM_BYTES>>>(p_tgt, W1, b1, W2, b2, W3, b3);
    jh_part_kernel<<<64, 128>>>(dt);
    jh_fin_kernel<<<8, 32>>>();
    for (int it = 0; it < 5; it++) {
        encode_kernel<1><<<dim3(NN/NP, BB), 256, SMEM_BYTES>>>(p_src, W1, b1, W2, b2, W3, b3);
        update_part_kernel<<<64, 128>>>();
        update_fin_kernel<<<8, 32>>>();
    }
    estg_kernel<<<1, 32>>>();
    loss_kernel<<<64, 256>>>(p_src);
    finish_kernel<<<(BB*KK + 256)/256 + 1, 256>>>(out, out_size);
}